// round 12
// baseline (speedup 1.0000x reference)
#include <cuda_runtime.h>
#include <cuda_bf16.h>
#include <math.h>
#include <float.h>
#include <limits.h>
#include <stdint.h>

// Problem constants
#define NTOK 4096      // B*S
#define DDIM 768
#define LDIM 256
#define VOC  50265
#define VOCP 50304     // 393 tiles of 128
#define NBLK 786       // 64-code blocks (VOCP/64)
#define BMAXP 788      // padded row
#define KSEL 4
#define NCAND 24

// ---------------- scratch (device globals; no allocations) ----------------
__device__ float  g_zi_pre[NTOK * LDIM];      // x@W_in+b (kept for mse2 ref)
__device__ float  g_zi[NTOK * LDIM];          // normalized
__device__ float  g_zc[VOC * LDIM];           // normalized latent codebook
__device__ float  g_zcn[VOC];                 // reciprocal norm: zc_pre = zc * g_zcn
__device__ signed char g_ziq[NTOK * LDIM];    // int8 quantized zi rows
__device__ signed char g_zcq[VOC * LDIM];     // int8 quantized zc rows
__device__ float  g_zisc[NTOK];               // zi row scale
__device__ float  g_zcsc[VOC];                // zc row scale
__device__ __nv_bfloat16 g_cbh[VOC * DDIM];   // bf16 hi split of codebook
__device__ __nv_bfloat16 g_cbl[VOC * DDIM];   // bf16 lo split of codebook
__device__ __nv_bfloat16 g_wth[LDIM * DDIM];  // W_code^T hi (n-major, k-contig)
__device__ __nv_bfloat16 g_wtl[LDIM * DDIM];  // W_code^T lo
__device__ __nv_bfloat16 g_scores[(size_t)NTOK * VOCP];   // all approx scores
__device__ __nv_bfloat16 g_bmax[(size_t)NTOK * BMAXP];    // per-64-block max
__device__ int    g_idx[NTOK * KSEL];
__device__ int    g_counts[VOC];
__device__ double g_mse1, g_mse2, g_ent;
__device__ int    g_nz;

// ---------------- helpers ----------------
__device__ __forceinline__ uint32_t smem_u32(const void* p) {
    uint32_t a;
    asm("{ .reg .u64 t; cvta.to.shared.u64 t, %1; cvt.u32.u64 %0, t; }" : "=r"(a) : "l"(p));
    return a;
}
__device__ __forceinline__ bool better(float v, int j, float v2, int j2) {
    return (v > v2) || (v == v2 && j < j2);
}
template <int K>
__device__ __forceinline__ void insK(float v, int j, float tv[K], int ti[K]) {
    if (!better(v, j, tv[K-1], ti[K-1])) return;
    tv[K-1] = v; ti[K-1] = j;
#pragma unroll
    for (int k = K-1; k > 0; k--) {
        if (better(tv[k], ti[k], tv[k-1], ti[k-1])) {
            float fv = tv[k]; tv[k] = tv[k-1]; tv[k-1] = fv;
            int   fi = ti[k]; ti[k] = ti[k-1]; ti[k-1] = fi;
        }
    }
}

// ---------------- mma + ldmatrix + cp.async helpers ----------------
__device__ __forceinline__ void mma_bf16(float d[4], const unsigned a[4], const unsigned b[2]) {
    asm("mma.sync.aligned.m16n8k16.row.col.f32.bf16.bf16.f32 "
        "{%0,%1,%2,%3},{%4,%5,%6,%7},{%8,%9},{%0,%1,%2,%3};"
        : "+f"(d[0]), "+f"(d[1]), "+f"(d[2]), "+f"(d[3])
        : "r"(a[0]), "r"(a[1]), "r"(a[2]), "r"(a[3]), "r"(b[0]), "r"(b[1]));
}
__device__ __forceinline__ void mma_s8(int d[4], const unsigned a[4], const unsigned b[2]) {
    asm("mma.sync.aligned.m16n8k32.row.col.s32.s8.s8.s32 "
        "{%0,%1,%2,%3},{%4,%5,%6,%7},{%8,%9},{%0,%1,%2,%3};"
        : "+r"(d[0]), "+r"(d[1]), "+r"(d[2]), "+r"(d[3])
        : "r"(a[0]), "r"(a[1]), "r"(a[2]), "r"(a[3]), "r"(b[0]), "r"(b[1]));
}
__device__ __forceinline__ void ldsm_x4(uint32_t addr, unsigned r[4]) {
    asm volatile("ldmatrix.sync.aligned.m8n8.x4.shared.b16 {%0,%1,%2,%3}, [%4];"
        : "=r"(r[0]), "=r"(r[1]), "=r"(r[2]), "=r"(r[3]) : "r"(addr));
}
__device__ __forceinline__ void cp16(uint32_t dst, const void* src, int ssz) {
    asm volatile("cp.async.cg.shared.global [%0], [%1], 16, %2;"
        :: "r"(dst), "l"(src), "r"(ssz) : "memory");
}
#define CP_COMMIT() asm volatile("cp.async.commit_group;" ::: "memory")
#define CP_WAIT0()  asm volatile("cp.async.wait_group 0;" ::: "memory")

// ---------------- init ----------------
__global__ void init_k() {
    int i = blockIdx.x * blockDim.x + threadIdx.x;
    for (int v = i; v < VOC; v += gridDim.x * blockDim.x) g_counts[v] = 0;
    if (i == 0) { g_mse1 = 0.0; g_mse2 = 0.0; g_ent = 0.0; g_nz = 0; }
}

// ---------------- bf16 hi/lo split of codebook (streaming) -----------------
__global__ void splitcb_k(const float4* __restrict__ in, uint2* __restrict__ oh,
                          uint2* __restrict__ ol, int n4)
{
    int i = blockIdx.x * blockDim.x + threadIdx.x;
    int stride = gridDim.x * blockDim.x;
    for (; i < n4; i += stride) {
        float4 v = in[i];
        __nv_bfloat16 h0 = __float2bfloat16(v.x);
        __nv_bfloat16 h1 = __float2bfloat16(v.y);
        __nv_bfloat16 h2 = __float2bfloat16(v.z);
        __nv_bfloat16 h3 = __float2bfloat16(v.w);
        __nv_bfloat16 l0 = __float2bfloat16(v.x - __bfloat162float(h0));
        __nv_bfloat16 l1 = __float2bfloat16(v.y - __bfloat162float(h1));
        __nv_bfloat16 l2 = __float2bfloat16(v.z - __bfloat162float(h2));
        __nv_bfloat16 l3 = __float2bfloat16(v.w - __bfloat162float(h3));
        __nv_bfloat162 hp0 = {h0, h1}, hp1 = {h2, h3};
        __nv_bfloat162 lp0 = {l0, l1}, lp1 = {l2, l3};
        uint2 uh, ul;
        uh.x = *(unsigned*)&hp0; uh.y = *(unsigned*)&hp1;
        ul.x = *(unsigned*)&lp0; ul.y = *(unsigned*)&lp1;
        oh[i] = uh; ol[i] = ul;
    }
}

// ---------------- transpose + split W_code: WcT[n][k] = Wc[k][n] -----------
__global__ void wsplit_k(const float* __restrict__ Wc,
                         __nv_bfloat16* __restrict__ wth, __nv_bfloat16* __restrict__ wtl)
{
    int idx = blockIdx.x * blockDim.x + threadIdx.x;
    if (idx >= LDIM * DDIM) return;
    int n = idx / DDIM, k = idx - n * DDIM;
    float v = Wc[k * LDIM + n];
    __nv_bfloat16 h = __float2bfloat16(v);
    wth[idx] = h;
    wtl[idx] = __float2bfloat16(v - __bfloat162float(h));
}

// ---------------- GEMM (R1 proven): zi projection, exact fp32 --------------
__global__ void __launch_bounds__(256, 2)
gemm_k(const float* __restrict__ A, const float* __restrict__ W,
       const float* __restrict__ bias, float* __restrict__ C, int M)
{
    __shared__ float As[32][68];   // k-major: As[k][m]
    __shared__ float Ws[32][68];   // Ws[k][n]
    const int tid = threadIdx.x;
    const int m0 = blockIdx.x * 64, n0 = blockIdx.y * 64;
    const int tx = tid & 15, ty = tid >> 4;

    float acc[4][4] = {};
    for (int c0 = 0; c0 < DDIM; c0 += 32) {
#pragma unroll
        for (int t = 0; t < 2; t++) {            // A tile -> transposed store
            int li = tid * 2 + t;
            int row = li >> 3, kq = li & 7;
            float4 v = make_float4(0.f, 0.f, 0.f, 0.f);
            if (m0 + row < M)
                v = *(const float4*)&A[(size_t)(m0 + row) * DDIM + c0 + kq * 4];
            As[kq*4+0][row] = v.x; As[kq*4+1][row] = v.y;
            As[kq*4+2][row] = v.z; As[kq*4+3][row] = v.w;
        }
#pragma unroll
        for (int t = 0; t < 2; t++) {            // W tile -> direct store
            int li = tid * 2 + t;
            int r = li >> 4, nq = li & 15;
            float4 v = *(const float4*)&W[(size_t)(c0 + r) * LDIM + n0 + nq * 4];
            *(float4*)&Ws[r][nq * 4] = v;
        }
        __syncthreads();
#pragma unroll
        for (int kk = 0; kk < 32; kk++) {
            float4 a4 = *(float4*)&As[kk][ty * 4];
            float4 b4 = *(float4*)&Ws[kk][tx * 4];
            float av[4] = {a4.x, a4.y, a4.z, a4.w};
            float bv[4] = {b4.x, b4.y, b4.z, b4.w};
#pragma unroll
            for (int i = 0; i < 4; i++)
#pragma unroll
                for (int j = 0; j < 4; j++)
                    acc[i][j] += av[i] * bv[j];
        }
        __syncthreads();
    }
#pragma unroll
    for (int i = 0; i < 4; i++) {
        int row = m0 + ty * 4 + i;
        if (row < M) {
#pragma unroll
            for (int j = 0; j < 4; j++) {
                int col = n0 + tx * 4 + j;
                C[(size_t)row * LDIM + col] = acc[i][j] + bias[col];
            }
        }
    }
}

// ---------------- zc GEMM via 3-product bf16-split tensor MMA --------------
__global__ void __launch_bounds__(256, 2)
zc_mma(const __nv_bfloat16* __restrict__ cbh, const __nv_bfloat16* __restrict__ cbl,
       const __nv_bfloat16* __restrict__ wth, const __nv_bfloat16* __restrict__ wtl,
       const float* __restrict__ bias, float* __restrict__ C)
{
    extern __shared__ __align__(16) char dynbuf[];
    const int tid = threadIdx.x;
    const int w = tid >> 5, lane = tid & 31;
    const int grp = lane >> 2, tig = lane & 3;
    const int wm = w >> 1, wn = w & 1;            // 4 x 2 warp grid
    const int m0 = blockIdx.x * 128;
    const int n0 = blockIdx.y * 128;
    const int lrow = tid >> 1;                    // loader row 0..127
    const int eo   = (tid & 1) * 16;

    const uint32_t sm0 = smem_u32(dynbuf);
    const uint32_t ldst = (uint32_t)(lrow * 80 + eo * 2);

    uint32_t offA[2], offB[4];
    {
        int la = lane & 15, ha = lane >> 4;
#pragma unroll
        for (int mi = 0; mi < 2; mi++)
            offA[mi] = (uint32_t)((wm * 32 + mi * 16 + la) * 80 + ha * 16);
        int rb = ((lane >> 4) & 1) * 8 + (lane & 7);
        int cbb = ((lane >> 3) & 1) * 16;
#pragma unroll
        for (int p = 0; p < 4; p++)
            offB[p] = (uint32_t)((wn * 64 + p * 16 + rb) * 80 + cbb);
    }

    float acc[2][8][4] = {};
    const int asz = (m0 + lrow < VOC) ? 16 : 0;   // zero-fill OOB codebook rows
    const __nv_bfloat16* ah_src = cbh + (size_t)(m0 + lrow) * DDIM + eo;
    const __nv_bfloat16* al_src = cbl + (size_t)(m0 + lrow) * DDIM + eo;
    const __nv_bfloat16* bh_src = wth + (size_t)(n0 + lrow) * DDIM + eo;
    const __nv_bfloat16* bl_src = wtl + (size_t)(n0 + lrow) * DDIM + eo;

    {
        uint32_t b = sm0;
        cp16(b + ldst,              ah_src,     asz);
        cp16(b + ldst + 16,         ah_src + 8, asz);
        cp16(b + 10240 + ldst,      al_src,     asz);
        cp16(b + 10240 + ldst + 16, al_src + 8, asz);
        cp16(b + 20480 + ldst,      bh_src,     16);
        cp16(b + 20480 + ldst + 16, bh_src + 8, 16);
        cp16(b + 30720 + ldst,      bl_src,     16);
        cp16(b + 30720 + ldst + 16, bl_src + 8, 16);
        CP_COMMIT();
    }

    for (int s = 0; s < 24; s++) {           // 24 stages of 32 k-dims
        CP_WAIT0();
        __syncthreads();
        if (s < 23) {
            int ko = (s + 1) * 32;
            uint32_t b = sm0 + (uint32_t)(((s + 1) & 1) * 40960);
            cp16(b + ldst,              ah_src + ko,     asz);
            cp16(b + ldst + 16,         ah_src + ko + 8, asz);
            cp16(b + 10240 + ldst,      al_src + ko,     asz);
            cp16(b + 10240 + ldst + 16, al_src + ko + 8, asz);
            cp16(b + 20480 + ldst,      bh_src + ko,     16);
            cp16(b + 20480 + ldst + 16, bh_src + ko + 8, 16);
            cp16(b + 30720 + ldst,      bl_src + ko,     16);
            cp16(b + 30720 + ldst + 16, bl_src + ko + 8, 16);
            CP_COMMIT();
        }
        uint32_t bb_ = sm0 + (uint32_t)((s & 1) * 40960);
        uint32_t sAh = bb_, sAl = bb_ + 10240, sBh = bb_ + 20480, sBl = bb_ + 30720;
#pragma unroll
        for (int ks = 0; ks < 2; ks++) {
            unsigned ah0[4], ah1[4], al0[4], al1[4];
            ldsm_x4(sAh + offA[0] + ks * 32, ah0);
            ldsm_x4(sAh + offA[1] + ks * 32, ah1);
            ldsm_x4(sAl + offA[0] + ks * 32, al0);
            ldsm_x4(sAl + offA[1] + ks * 32, al1);
#pragma unroll
            for (int p = 0; p < 4; p++) {
                unsigned bh[4], bl[4];
                ldsm_x4(sBh + offB[p] + ks * 32, bh);
                ldsm_x4(sBl + offB[p] + ks * 32, bl);
                mma_bf16(acc[0][2*p],     ah0, bh);
                mma_bf16(acc[0][2*p + 1], ah0, bh + 2);
                mma_bf16(acc[1][2*p],     ah1, bh);
                mma_bf16(acc[1][2*p + 1], ah1, bh + 2);
                mma_bf16(acc[0][2*p],     ah0, bl);
                mma_bf16(acc[0][2*p + 1], ah0, bl + 2);
                mma_bf16(acc[1][2*p],     ah1, bl);
                mma_bf16(acc[1][2*p + 1], ah1, bl + 2);
                mma_bf16(acc[0][2*p],     al0, bh);
                mma_bf16(acc[0][2*p + 1], al0, bh + 2);
                mma_bf16(acc[1][2*p],     al1, bh);
                mma_bf16(acc[1][2*p + 1], al1, bh + 2);
            }
        }
    }

#pragma unroll
    for (int mi = 0; mi < 2; mi++)
#pragma unroll
    for (int h = 0; h < 2; h++) {
        int row = m0 + wm * 32 + mi * 16 + grp + h * 8;
        if (row < VOC) {
#pragma unroll
            for (int ni = 0; ni < 8; ni++) {
                int col = n0 + wn * 64 + ni * 8 + tig * 2;
                float2 v;
                v.x = acc[mi][ni][2*h]     + bias[col];
                v.y = acc[mi][ni][2*h + 1] + bias[col + 1];
                *(float2*)&C[(size_t)row * LDIM + col] = v;
            }
        }
    }
}

// ---------------- row L2-normalize, fused int8 quant (+ optional recip) ----
__global__ void norm_k(const float* __restrict__ in, float* __restrict__ out,
                       signed char* __restrict__ outq, float* __restrict__ qsc,
                       float* __restrict__ rnorm, int M)
{
    int w = (blockIdx.x * blockDim.x + threadIdx.x) >> 5;
    int lane = threadIdx.x & 31;
    if (w >= M) return;
    const float* r = in + (size_t)w * LDIM;
    float vals[8];
    float s = 0.f;
#pragma unroll
    for (int i = 0; i < 8; i++) { vals[i] = r[lane + 32 * i]; s += vals[i] * vals[i]; }
#pragma unroll
    for (int off = 16; off > 0; off >>= 1)
        s += __shfl_xor_sync(0xFFFFFFFFu, s, off);
    float t = s + 1e-12f;
    float sc = rsqrtf(t);
    sc = sc * (1.5f - 0.5f * t * sc * sc);   // Newton: ~1 ulp
    float* o = out + (size_t)w * LDIM;
    float amax = 0.f;
#pragma unroll
    for (int i = 0; i < 8; i++) {
        vals[i] *= sc;
        o[lane + 32 * i] = vals[i];
        amax = fmaxf(amax, fabsf(vals[i]));
    }
#pragma unroll
    for (int off = 16; off > 0; off >>= 1)
        amax = fmaxf(amax, __shfl_xor_sync(0xFFFFFFFFu, amax, off));
    float inv = 127.0f / amax;
    signed char* oq = outq + (size_t)w * LDIM;
#pragma unroll
    for (int i = 0; i < 8; i++) {
        int q = __float2int_rn(vals[i] * inv);
        oq[lane + 32 * i] = (signed char)q;
    }
    if (lane == 0) {
        qsc[w] = amax * (1.0f / 127.0f);
        if (rnorm) rnorm[w] = 1.0f / sc;
    }
}

// ---------------- K1: int8 IMMA scores -> bf16 store + 64-block max --------
// grid (NTOK/128, VOCP/128). Same byte layout as bf16 path: a 32B row-chunk
// is k32*s8 instead of k16*bf16; K=256 s8 in 4 double-buffered 64B stages.
__global__ void __launch_bounds__(256, 2)
score_imma(const signed char* __restrict__ ziq, const signed char* __restrict__ zcq,
           const float* __restrict__ zisc, const float* __restrict__ zcsc,
           __nv_bfloat16* __restrict__ scores, __nv_bfloat16* __restrict__ bmax)
{
    __shared__ __align__(16) char smembuf[40960];
    __shared__ float sash[128], sbsh[128];
    const int tid = threadIdx.x;
    const int w = tid >> 5, lane = tid & 31;
    const int grp = lane >> 2, tig = lane & 3;
    const int wm = w >> 1, wn = w & 1;            // 4 x 2 warp grid
    const int t0 = blockIdx.x * 128;
    const int jc = blockIdx.y * 128;

    const int lrow = tid >> 1;                    // loader row 0..127
    const int eo_b = (tid & 1) * 32;              // byte offset within 64B stage row

    // stage scales for epilogue
    if (tid < 128) sash[tid] = zisc[t0 + tid];
    else {
        int j = jc + tid - 128;
        sbsh[tid - 128] = (j < VOC) ? zcsc[j] : 0.f;
    }

    const uint32_t sm0 = smem_u32(smembuf);
    const uint32_t stA[2] = {sm0,         sm0 + 10240};
    const uint32_t stB[2] = {sm0 + 20480, sm0 + 30720};

    uint32_t offA[2], offB[4];
    {
        int la = lane & 15, ha = lane >> 4;
#pragma unroll
        for (int mi = 0; mi < 2; mi++)
            offA[mi] = (uint32_t)((wm * 32 + mi * 16 + la) * 80 + ha * 16);
        int rb = ((lane >> 4) & 1) * 8 + (lane & 7);
        int cbb = ((lane >> 3) & 1) * 16;
#pragma unroll
        for (int p = 0; p < 4; p++)
            offB[p] = (uint32_t)((wn * 64 + p * 16 + rb) * 80 + cbb);
    }

    int acc[2][8][4] = {};
    int jrow = jc + lrow;
    const int bsz = (jrow < VOC) ? 16 : 0;        // cp.async zero-fill OOB rows
    const signed char* arow = ziq + (size_t)(t0 + lrow) * LDIM + eo_b;
    const signed char* brow = zcq + (size_t)jrow * LDIM + eo_b;
    const uint32_t ldst = (uint32_t)(lrow * 80 + eo_b);

    // prologue: async stage 0 (64 bytes/row per stage)
    cp16(stA[0] + ldst,      arow,      16);
    cp16(stA[0] + ldst + 16, arow + 16, 16);
    cp16(stB[0] + ldst,      brow,      bsz);
    cp16(stB[0] + ldst + 16, brow + 16, bsz);
    CP_COMMIT();

#pragma unroll
    for (int s = 0; s < 4; s++) {            // 4 stages of 64 k-dims (s8)
        CP_WAIT0();
        __syncthreads();
        if (s < 3) {
            int ko = (s + 1) * 64;
            uint32_t dA = stA[(s + 1) & 1] + ldst;
            uint32_t dB = stB[(s + 1) & 1] + ldst;
            cp16(dA,      arow + ko,      16);
            cp16(dA + 16, arow + ko + 16, 16);
            cp16(dB,      brow + ko,      bsz);
            cp16(dB + 16, brow + ko + 16, bsz);
            CP_COMMIT();
        }
        const uint32_t sA = stA[s & 1], sB = stB[s & 1];
#pragma unroll
        for (int ks = 0; ks < 2; ks++) {     // two k32 sub-chunks of 32B
            unsigned a0[4], a1[4];
            ldsm_x4(sA + offA[0] + ks * 32, a0);
            ldsm_x4(sA + offA[1] + ks * 32, a1);
#pragma unroll
            for (int p = 0; p < 4; p++) {
                unsigned bb[4];
                ldsm_x4(sB + offB[p] + ks * 32, bb);
                mma_s8(acc[0][2*p],     a0, bb);
                mma_s8(acc[0][2*p + 1], a0, bb + 2);
                mma_s8(acc[1][2*p],     a1, bb);
                mma_s8(acc[1][2*p + 1], a1, bb + 2);
            }
        }
    }

    // ---- epilogue: scale to float, cvt bf16, store, packed block-max ------
    const int colbase = wn * 64 + tig * 2;
#pragma unroll
    for (int mi = 0; mi < 2; mi++)
#pragma unroll
    for (int h = 0; h < 2; h++) {
        int row_l = wm * 32 + mi * 16 + grp + h * 8;
        float sa = sash[row_l];
        size_t rowoff = (size_t)(t0 + row_l) * VOCP;
        unsigned p[8];
#pragma unroll
        for (int ni = 0; ni < 8; ni++) {
            int c = colbase + ni * 8;
            float2 f2;
            f2.x = (float)acc[mi][ni][2*h]     * (sa * sbsh[c]);
            f2.y = (float)acc[mi][ni][2*h + 1] * (sa * sbsh[c + 1]);
            __nv_bfloat162 bb = __float22bfloat162_rn(f2);   // .x -> low half
            p[ni] = *(unsigned*)&bb;
        }
        if (jc + 128 > VOC) {        // mask tail columns with bf16 -inf
#pragma unroll
            for (int ni = 0; ni < 8; ni++) {
                int j = jc + colbase + ni * 8;
                if (j >= VOC)     p[ni] = (p[ni] & 0xFFFF0000u) | 0x0000FF80u;
                if (j + 1 >= VOC) p[ni] = (p[ni] & 0x0000FFFFu) | 0xFF800000u;
            }
        }
#pragma unroll
        for (int ni = 0; ni < 8; ni++)
            *(unsigned*)(scores + rowoff + jc + colbase + ni * 8) = p[ni];
        // packed max tree over this thread's 16 cols, then across tig quad
        __nv_bfloat162 m = *(__nv_bfloat162*)&p[0];
#pragma unroll
        for (int ni = 1; ni < 8; ni++) m = __hmax2(m, *(__nv_bfloat162*)&p[ni]);
        unsigned mu = *(unsigned*)&m;
        unsigned o1 = __shfl_xor_sync(0xFFFFFFFFu, mu, 1);
        m = __hmax2(m, *(__nv_bfloat162*)&o1);
        mu = *(unsigned*)&m;
        unsigned o2 = __shfl_xor_sync(0xFFFFFFFFu, mu, 2);
        m = __hmax2(m, *(__nv_bfloat162*)&o2);
        if (tig == 0) {
            __nv_bfloat16 ms = __hmax(m.x, m.y);
            bmax[(size_t)(t0 + row_l) * BMAXP + (jc >> 6) + wn] = ms;
        }
    }
}

// ---------------- K2: block select + candidate prune + exact top-4 --------
__global__ void __launch_bounds__(128)
select_k(const __nv_bfloat16* __restrict__ bmax, const __nv_bfloat16* __restrict__ scores,
         const float* __restrict__ zi, const float* __restrict__ zc)
{
    __shared__ int scand[4][NCAND];
    const int wl = threadIdx.x >> 5;
    const int t = (blockIdx.x * blockDim.x + threadIdx.x) >> 5;
    const int lane = threadIdx.x & 31;
    if (t >= NTOK) return;

    // Phase A: lane-local top-8 of 786 blockmaxes
    float lv[8]; int lb[8];
#pragma unroll
    for (int k = 0; k < 8; k++) { lv[k] = -FLT_MAX; lb[k] = INT_MAX; }
    const __nv_bfloat16* bm = bmax + (size_t)t * BMAXP;
#pragma unroll
    for (int k = 0; k < 25; k++) {
        int b = lane + 32 * k;
        if (b < NBLK) {
            float v = __bfloat162float(bm[b]);
            if (v >= lv[7]) insK<8>(v, b, lv, lb);
        }
    }
    // extract top-16 blocks (warp-wide argmax, owner pops)
    int blk[16];
#pragma unroll
    for (int r = 0; r < 16; r++) {
        float cv = lv[0]; int cb = lb[0];
#pragma unroll
        for (int off = 16; off > 0; off >>= 1) {
            float ov = __shfl_xor_sync(0xFFFFFFFFu, cv, off);
            int   ob = __shfl_xor_sync(0xFFFFFFFFu, cb, off);
            if (better(ov, ob, cv, cb)) { cv = ov; cb = ob; }
        }
        blk[r] = cb;
        if (lb[0] == cb) {
#pragma unroll
            for (int k = 0; k < 7; k++) { lv[k] = lv[k+1]; lb[k] = lb[k+1]; }
            lv[7] = -FLT_MAX; lb[7] = INT_MAX;
        }
    }

    // Phase B: lane-local top-12 over the 16 blocks' 1024 bf16 scores
    float cv12[12]; int ci12[12];
#pragma unroll
    for (int k = 0; k < 12; k++) { cv12[k] = -FLT_MAX; ci12[k] = INT_MAX; }
    const __nv_bfloat16* srow = scores + (size_t)t * VOCP;
#pragma unroll
    for (int r = 0; r < 16; r++) {
        int j0 = blk[r] * 64 + lane * 2;
        unsigned u = *(const unsigned*)(srow + j0);
        __nv_bfloat162 b2 = *(__nv_bfloat162*)&u;
        float f0 = __bfloat162float(b2.x);
        float f1 = __bfloat162float(b2.y);
        if (f0 >= cv12[11]) insK<12>(f0, j0,     cv12, ci12);
        if (f1 >= cv12[11]) insK<12>(f1, j0 + 1, cv12, ci12);
    }
    // Phase C: extract top-24 candidates into smem
#pragma unroll
    for (int r = 0; r < NCAND; r++) {
        float cv = cv12[0]; int cb = ci12[0];
#pragma unroll
        for (int off = 16; off > 0; off >>= 1) {
            float ov = __shfl_xor_sync(0xFFFFFFFFu, cv, off);
            int   ob = __shfl_xor_sync(0xFFFFFFFFu, cb, off);
            if (better(ov, ob, cv, cb)) { cv = ov; cb = ob; }
        }
        if (lane == 0) scand[wl][r] = cb;
        if (ci12[0] == cb) {
#pragma unroll
            for (int k = 0; k < 11; k++) { cv12[k] = cv12[k+1]; ci12[k] = ci12[k+1]; }
            cv12[11] = -FLT_MAX; ci12[11] = INT_MAX;
        }
    }
    __syncwarp();

    // Phase D: exact fp32 rescore of 24 candidates -> top-4 + histogram
    const float* zr = zi + (size_t)t * LDIM;
    float a[8];
#pragma unroll
    for (int i = 0; i < 8; i++) a[i] = zr[lane + 32 * i];
    float tv[4] = {-FLT_MAX, -FLT_MAX, -FLT_MAX, -FLT_MAX};
    int   ti[4] = {INT_MAX, INT_MAX, INT_MAX, INT_MAX};
    for (int c = 0; c < NCAND; c += 2) {
        int j0c = scand[wl][c], j1c = scand[wl][c + 1];
        const float* b0 = zc + (size_t)j0c * LDIM;
        const float* b1 = zc + (size_t)j1c * LDIM;
        float s0 = 0.f, s1 = 0.f;
#pragma unroll
        for (int i = 0; i < 8; i++) {
            s0 += a[i] * b0[lane + 32 * i];
            s1 += a[i] * b1[lane + 32 * i];
        }
#pragma unroll
        for (int off = 16; off > 0; off >>= 1) {
            s0 += __shfl_xor_sync(0xFFFFFFFFu, s0, off);
            s1 += __shfl_xor_sync(0xFFFFFFFFu, s1, off);
        }
        insK<4>(s0, j0c, tv, ti);
        insK<4>(s1, j1c, tv, ti);
    }
    if (lane == 0) {
#pragma unroll
        for (int k = 0; k < 4; k++) {
            g_idx[t * 4 + k] = ti[k];
            atomicAdd(&g_counts[ti[k]], 1);
        }
    }
}

// ---------------- quantize + STE out + mse1 --------------------------------
__global__ void quant_k(const float* __restrict__ x, const float* __restrict__ cb,
                        float* __restrict__ out)
{
    int w = (blockIdx.x * blockDim.x + threadIdx.x) >> 5;   // token
    int lane = threadIdx.x & 31;
    if (w >= NTOK) return;
    const float* c0 = cb + (size_t)g_idx[w * 4 + 0] * DDIM;
    const float* c1 = cb + (size_t)g_idx[w * 4 + 1] * DDIM;
    const float* c2 = cb + (size_t)g_idx[w * 4 + 2] * DDIM;
    const float* c3 = cb + (size_t)g_idx[w * 4 + 3] * DDIM;
    double s = 0.0;
    for (int c = lane; c < DDIM; c += 32) {
        float qv = (((c0[c] + c1[c]) + c2[c]) + c3[c]) * 0.25f;
        float xv = x[(size_t)w * DDIM + c];
        float d = qv - xv;
        out[(size_t)w * DDIM + c] = xv + d;     // x + (q - x), matches STE
        s += (double)d * (double)d;
    }
#pragma unroll
    for (int off = 16; off > 0; off >>= 1)
        s += __shfl_down_sync(0xFFFFFFFFu, s, off);
    if (lane == 0) atomicAdd(&g_mse1, s);
}

// ---------------- mse2 via zc reuse: q@Wc+b == mean_k zc_pre[j_k] ----------
__global__ void mse2_k(const float* __restrict__ zc, const float* __restrict__ rn,
                       const float* __restrict__ zi_pre)
{
    int t = (blockIdx.x * blockDim.x + threadIdx.x) >> 5;
    int lane = threadIdx.x & 31;
    if (t >= NTOK) return;
    int j0 = g_idx[t * 4 + 0], j1 = g_idx[t * 4 + 1];
    int j2 = g_idx[t * 4 + 2], j3 = g_idx[t * 4 + 3];
    float w0 = 0.25f * rn[j0], w1 = 0.25f * rn[j1];
    float w2 = 0.25f * rn[j2], w3 = 0.25f * rn[j3];
    const float* z0 = zc + (size_t)j0 * LDIM;
    const float* z1 = zc + (size_t)j1 * LDIM;
    const float* z2 = zc + (size_t)j2 * LDIM;
    const float* z3 = zc + (size_t)j3 * LDIM;
    const float* rp = zi_pre + (size_t)t * LDIM;
    double s = 0.0;
#pragma unroll
    for (int i = 0; i < 8; i++) {
        int c = lane + 32 * i;
        float v = z0[c] * w0 + z1[c] * w1 + z2[c] * w2 + z3[c] * w3 - rp[c];
        s += (double)v * (double)v;
    }
#pragma unroll
    for (int off = 16; off > 0; off >>= 1)
        s += __shfl_down_sync(0xFFFFFFFFu, s, off);
    if (lane == 0) atomicAdd(&g_mse2, s);
}

// ---------------- entropy / usage ------------------------------------------
__global__ void ent_k()
{
    int i0 = blockIdx.x * blockDim.x + threadIdx.x;
    double e = 0.0; int nz = 0;
    for (int i = i0; i < VOC; i += gridDim.x * blockDim.x) {
        int c = g_counts[i];
        if (c > 0) {
            float p = (float)c * (1.0f / (NTOK * KSEL));
            e += (double)(p * logf(p + 1e-10f));
            nz++;
        }
    }
#pragma unroll
    for (int off = 16; off > 0; off >>= 1) {
        e  += __shfl_down_sync(0xFFFFFFFFu, e, off);
        nz += __shfl_down_sync(0xFFFFFFFFu, nz, off);
    }
    if ((threadIdx.x & 31) == 0) { atomicAdd(&g_ent, e); atomicAdd(&g_nz, nz); }
}

// ---------------- finalize scalars -----------------------------------------
__global__ void fin_k(float* __restrict__ out3)
{
    float lp = (float)(-g_ent);
    float mse1 = (float)(g_mse1 / ((double)NTOK * DDIM));
    float mse2 = (float)(g_mse2 / ((double)NTOK * LDIM));
    float loss = 1.25f * mse1 + 1.25f * mse2 + 0.1f * lp;
    out3[0] = loss;
    out3[1] = expf(lp);
    out3[2] = (float)g_nz / (float)VOC / (float)KSEL;
}

// ---------------- launch ----------------------------------------------------
static float* sym_f(const void* s) { void* p = nullptr; cudaGetSymbolAddress(&p, s); return (float*)p; }
static __nv_bfloat16* sym_b(const void* s) { void* p = nullptr; cudaGetSymbolAddress(&p, s); return (__nv_bfloat16*)p; }
static signed char* sym_c(const void* s) { void* p = nullptr; cudaGetSymbolAddress(&p, s); return (signed char*)p; }

#define ZCMMA_SMEM 81920

extern "C" void kernel_launch(void* const* d_in, const int* in_sizes, int n_in,
                              void* d_out, int out_size)
{
    const float* x  = (const float*)d_in[0];
    const float* cb = (const float*)d_in[1];
    const float* Wi = (const float*)d_in[2];
    const float* bi = (const float*)d_in[3];
    const float* Wc = (const float*)d_in[4];
    const float* bc = (const float*)d_in[5];
    float* out = (float*)d_out;

    float* zi_pre = sym_f(g_zi_pre);
    float* zi     = sym_f(g_zi);
    float* zc     = sym_f(g_zc);
    float* zcn    = sym_f(g_zcn);
    float* zisc   = sym_f(g_zisc);
    float* zcsc   = sym_f(g_zcsc);
    signed char* ziq = sym_c(g_ziq);
    signed char* zcq = sym_c(g_zcq);
    __nv_bfloat16* cbh = sym_b(g_cbh);
    __nv_bfloat16* cbl = sym_b(g_cbl);
    __nv_bfloat16* wth = sym_b(g_wth);
    __nv_bfloat16* wtl = sym_b(g_wtl);
    __nv_bfloat16* scores = sym_b(g_scores);
    __nv_bfloat16* bmax   = sym_b(g_bmax);

    cudaFuncSetAttribute(zc_mma, cudaFuncAttributeMaxDynamicSharedMemorySize, ZCMMA_SMEM);

    init_k<<<64, 256>>>();
    // bf16 hi/lo splits of codebook + W_code^T
    splitcb_k<<<1024, 256>>>((const float4*)cb, (uint2*)cbh, (uint2*)cbl,
                             VOC * DDIM / 4);
    wsplit_k<<<(LDIM * DDIM + 255) / 256, 256>>>(Wc, wth, wtl);
    // zi_pre = x @ W_in + b_in ; zi = l2n(zi_pre) (+ int8 quant)  [exact fp32]
    gemm_k<<<dim3(NTOK / 64, LDIM / 64), 256>>>(x, Wi, bi, zi_pre, NTOK);
    norm_k<<<NTOK / 8, 256>>>(zi_pre, zi, ziq, zisc, nullptr, NTOK);
    // zc_pre = cb @ W_code + b_code via 3-product bf16-split tensor MMA
    zc_mma<<<dim3((VOC + 127) / 128, LDIM / 128), 256, ZCMMA_SMEM>>>(
        cbh, cbl, wth, wtl, bc, zc);
    norm_k<<<(VOC + 7) / 8, 256>>>(zc, zc, zcq, zcsc, zcn, VOC);
    // K1: int8 IMMA scores -> gmem + blockmax
    score_imma<<<dim3(NTOK / 128, VOCP / 128), 256>>>(ziq, zcq, zisc, zcsc,
                                                      scores, bmax);
    // K2: block-select + prune + exact top-4 + histogram
    select_k<<<NTOK / 4, 128>>>(bmax, scores, zi, zc);
    // quantize + STE output + mse1
    quant_k<<<NTOK / 8, 256>>>(x, cb, out);
    // mse2 without a GEMM: q@Wc+b == mean of selected zc_pre rows
    mse2_k<<<NTOK / 8, 256>>>(zc, zcn, zi_pre);
    ent_k<<<64, 256>>>();
    fin_k<<<1, 1>>>(out + (size_t)NTOK * DDIM);
}

// round 13
// speedup vs baseline: 1.3379x; 1.3379x over previous
#include <cuda_runtime.h>
#include <cuda_bf16.h>
#include <math.h>
#include <float.h>
#include <limits.h>
#include <stdint.h>

// Problem constants
#define NTOK 4096      // B*S
#define DDIM 768
#define LDIM 256
#define VOC  50265
#define VOCP 50304     // 393 tiles of 128
#define NBLK 786       // 64-code blocks (VOCP/64)
#define BMAXP 788      // padded row
#define KSEL 4
#define NCAND 24

// ---------------- scratch (device globals; no allocations) ----------------
__device__ float  g_zi_pre[NTOK * LDIM];      // x@W_in+b (kept for mse2 ref)
__device__ float  g_zi[NTOK * LDIM];          // normalized
__device__ float  g_zc[VOC * LDIM];           // normalized latent codebook
__device__ float  g_zcn[VOC];                 // reciprocal norm: zc_pre = zc * g_zcn
__device__ __nv_bfloat16 g_zih[NTOK * LDIM];
__device__ __nv_bfloat16 g_zch[VOC * LDIM];
__device__ __nv_bfloat16 g_cbh[VOC * DDIM];   // bf16 hi split of codebook
__device__ __nv_bfloat16 g_cbl[VOC * DDIM];   // bf16 lo split of codebook
__device__ __nv_bfloat16 g_xh[NTOK * DDIM];   // bf16 hi split of x
__device__ __nv_bfloat16 g_xl[NTOK * DDIM];   // bf16 lo split of x
__device__ __nv_bfloat16 g_wth[LDIM * DDIM];  // W_code^T hi (n-major, k-contig)
__device__ __nv_bfloat16 g_wtl[LDIM * DDIM];  // W_code^T lo
__device__ __nv_bfloat16 g_wih[LDIM * DDIM];  // W_in^T hi
__device__ __nv_bfloat16 g_wil[LDIM * DDIM];  // W_in^T lo
__device__ __nv_bfloat16 g_scores[(size_t)NTOK * VOCP];   // all approx scores
__device__ __nv_bfloat16 g_bmax[(size_t)NTOK * BMAXP];    // per-64-block max
__device__ int    g_idx[NTOK * KSEL];
__device__ int    g_counts[VOC];
__device__ double g_mse1, g_mse2, g_ent;
__device__ int    g_nz;

// ---------------- helpers ----------------
__device__ __forceinline__ uint32_t smem_u32(const void* p) {
    uint32_t a;
    asm("{ .reg .u64 t; cvta.to.shared.u64 t, %1; cvt.u32.u64 %0, t; }" : "=r"(a) : "l"(p));
    return a;
}
__device__ __forceinline__ bool better(float v, int j, float v2, int j2) {
    return (v > v2) || (v == v2 && j < j2);
}
template <int K>
__device__ __forceinline__ void insK(float v, int j, float tv[K], int ti[K]) {
    if (!better(v, j, tv[K-1], ti[K-1])) return;
    tv[K-1] = v; ti[K-1] = j;
#pragma unroll
    for (int k = K-1; k > 0; k--) {
        if (better(tv[k], ti[k], tv[k-1], ti[k-1])) {
            float fv = tv[k]; tv[k] = tv[k-1]; tv[k-1] = fv;
            int   fi = ti[k]; ti[k] = ti[k-1]; ti[k-1] = fi;
        }
    }
}

// ---------------- bf16 mma + ldmatrix + cp.async helpers ----------------
__device__ __forceinline__ void mma_bf16(float d[4], const unsigned a[4], const unsigned b[2]) {
    asm("mma.sync.aligned.m16n8k16.row.col.f32.bf16.bf16.f32 "
        "{%0,%1,%2,%3},{%4,%5,%6,%7},{%8,%9},{%0,%1,%2,%3};"
        : "+f"(d[0]), "+f"(d[1]), "+f"(d[2]), "+f"(d[3])
        : "r"(a[0]), "r"(a[1]), "r"(a[2]), "r"(a[3]), "r"(b[0]), "r"(b[1]));
}
__device__ __forceinline__ void ldsm_x4(uint32_t addr, unsigned r[4]) {
    asm volatile("ldmatrix.sync.aligned.m8n8.x4.shared.b16 {%0,%1,%2,%3}, [%4];"
        : "=r"(r[0]), "=r"(r[1]), "=r"(r[2]), "=r"(r[3]) : "r"(addr));
}
__device__ __forceinline__ void cp16(uint32_t dst, const void* src, int ssz) {
    asm volatile("cp.async.cg.shared.global [%0], [%1], 16, %2;"
        :: "r"(dst), "l"(src), "r"(ssz) : "memory");
}
#define CP_COMMIT() asm volatile("cp.async.commit_group;" ::: "memory")
#define CP_WAIT0()  asm volatile("cp.async.wait_group 0;" ::: "memory")

// ---------------- init ----------------
__global__ void init_k() {
    int i = blockIdx.x * blockDim.x + threadIdx.x;
    for (int v = i; v < VOC; v += gridDim.x * blockDim.x) g_counts[v] = 0;
    if (i == 0) { g_mse1 = 0.0; g_mse2 = 0.0; g_ent = 0.0; g_nz = 0; }
}

// ---------------- bf16 hi/lo split of a fp32 matrix (streaming) ------------
__global__ void split_k(const float4* __restrict__ in, uint2* __restrict__ oh,
                        uint2* __restrict__ ol, int n4)
{
    int i = blockIdx.x * blockDim.x + threadIdx.x;
    int stride = gridDim.x * blockDim.x;
    for (; i < n4; i += stride) {
        float4 v = in[i];
        __nv_bfloat16 h0 = __float2bfloat16(v.x);
        __nv_bfloat16 h1 = __float2bfloat16(v.y);
        __nv_bfloat16 h2 = __float2bfloat16(v.z);
        __nv_bfloat16 h3 = __float2bfloat16(v.w);
        __nv_bfloat16 l0 = __float2bfloat16(v.x - __bfloat162float(h0));
        __nv_bfloat16 l1 = __float2bfloat16(v.y - __bfloat162float(h1));
        __nv_bfloat16 l2 = __float2bfloat16(v.z - __bfloat162float(h2));
        __nv_bfloat16 l3 = __float2bfloat16(v.w - __bfloat162float(h3));
        __nv_bfloat162 hp0 = {h0, h1}, hp1 = {h2, h3};
        __nv_bfloat162 lp0 = {l0, l1}, lp1 = {l2, l3};
        uint2 uh, ul;
        uh.x = *(unsigned*)&hp0; uh.y = *(unsigned*)&hp1;
        ul.x = *(unsigned*)&lp0; ul.y = *(unsigned*)&lp1;
        oh[i] = uh; ol[i] = ul;
    }
}

// ---------------- transpose + split W [768,256] -> WT hi/lo [256,768] ------
__global__ void wsplit_k(const float* __restrict__ W,
                         __nv_bfloat16* __restrict__ wh, __nv_bfloat16* __restrict__ wl)
{
    int idx = blockIdx.x * blockDim.x + threadIdx.x;
    if (idx >= LDIM * DDIM) return;
    int n = idx / DDIM, k = idx - n * DDIM;
    float v = W[k * LDIM + n];
    __nv_bfloat16 h = __float2bfloat16(v);
    wh[idx] = h;
    wl[idx] = __float2bfloat16(v - __bfloat162float(h));
}

// ---------------- projection GEMM via 3-product bf16-split tensor MMA ------
// C[row,col] = sum_k (ah+al)[row,k]*(bh+bl)[col,k] + bias[col], K=DDIM
// products hh + hl + lh (ll dropped: ~3e-7 abs). grid (ceil(M/128), 2).
__global__ void __launch_bounds__(256, 2)
proj_mma(const __nv_bfloat16* __restrict__ ah_g, const __nv_bfloat16* __restrict__ al_g,
         const __nv_bfloat16* __restrict__ bh_g, const __nv_bfloat16* __restrict__ bl_g,
         const float* __restrict__ bias, float* __restrict__ C, int Mrows)
{
    extern __shared__ __align__(16) char dynbuf[];
    const int tid = threadIdx.x;
    const int w = tid >> 5, lane = tid & 31;
    const int grp = lane >> 2, tig = lane & 3;
    const int wm = w >> 1, wn = w & 1;            // 4 x 2 warp grid
    const int m0 = blockIdx.x * 128;
    const int n0 = blockIdx.y * 128;
    const int lrow = tid >> 1;                    // loader row 0..127
    const int eo   = (tid & 1) * 16;

    const uint32_t sm0 = smem_u32(dynbuf);
    const uint32_t ldst = (uint32_t)(lrow * 80 + eo * 2);

    uint32_t offA[2], offB[4];
    {
        int la = lane & 15, ha = lane >> 4;
#pragma unroll
        for (int mi = 0; mi < 2; mi++)
            offA[mi] = (uint32_t)((wm * 32 + mi * 16 + la) * 80 + ha * 16);
        int rb = ((lane >> 4) & 1) * 8 + (lane & 7);
        int cbb = ((lane >> 3) & 1) * 16;
#pragma unroll
        for (int p = 0; p < 4; p++)
            offB[p] = (uint32_t)((wn * 64 + p * 16 + rb) * 80 + cbb);
    }

    float acc[2][8][4] = {};
    const int asz = (m0 + lrow < Mrows) ? 16 : 0; // zero-fill OOB rows
    const __nv_bfloat16* ah_src = ah_g + (size_t)(m0 + lrow) * DDIM + eo;
    const __nv_bfloat16* al_src = al_g + (size_t)(m0 + lrow) * DDIM + eo;
    const __nv_bfloat16* bh_src = bh_g + (size_t)(n0 + lrow) * DDIM + eo;
    const __nv_bfloat16* bl_src = bl_g + (size_t)(n0 + lrow) * DDIM + eo;

    {
        uint32_t b = sm0;
        cp16(b + ldst,              ah_src,     asz);
        cp16(b + ldst + 16,         ah_src + 8, asz);
        cp16(b + 10240 + ldst,      al_src,     asz);
        cp16(b + 10240 + ldst + 16, al_src + 8, asz);
        cp16(b + 20480 + ldst,      bh_src,     16);
        cp16(b + 20480 + ldst + 16, bh_src + 8, 16);
        cp16(b + 30720 + ldst,      bl_src,     16);
        cp16(b + 30720 + ldst + 16, bl_src + 8, 16);
        CP_COMMIT();
    }

    for (int s = 0; s < 24; s++) {           // 24 stages of 32 k-dims
        CP_WAIT0();
        __syncthreads();
        if (s < 23) {
            int ko = (s + 1) * 32;
            uint32_t b = sm0 + (uint32_t)(((s + 1) & 1) * 40960);
            cp16(b + ldst,              ah_src + ko,     asz);
            cp16(b + ldst + 16,         ah_src + ko + 8, asz);
            cp16(b + 10240 + ldst,      al_src + ko,     asz);
            cp16(b + 10240 + ldst + 16, al_src + ko + 8, asz);
            cp16(b + 20480 + ldst,      bh_src + ko,     16);
            cp16(b + 20480 + ldst + 16, bh_src + ko + 8, 16);
            cp16(b + 30720 + ldst,      bl_src + ko,     16);
            cp16(b + 30720 + ldst + 16, bl_src + ko + 8, 16);
            CP_COMMIT();
        }
        uint32_t bb_ = sm0 + (uint32_t)((s & 1) * 40960);
        uint32_t sAh = bb_, sAl = bb_ + 10240, sBh = bb_ + 20480, sBl = bb_ + 30720;
#pragma unroll
        for (int ks = 0; ks < 2; ks++) {
            unsigned ah0[4], ah1[4], al0[4], al1[4];
            ldsm_x4(sAh + offA[0] + ks * 32, ah0);
            ldsm_x4(sAh + offA[1] + ks * 32, ah1);
            ldsm_x4(sAl + offA[0] + ks * 32, al0);
            ldsm_x4(sAl + offA[1] + ks * 32, al1);
#pragma unroll
            for (int p = 0; p < 4; p++) {
                unsigned bh[4], bl[4];
                ldsm_x4(sBh + offB[p] + ks * 32, bh);
                ldsm_x4(sBl + offB[p] + ks * 32, bl);
                mma_bf16(acc[0][2*p],     ah0, bh);
                mma_bf16(acc[0][2*p + 1], ah0, bh + 2);
                mma_bf16(acc[1][2*p],     ah1, bh);
                mma_bf16(acc[1][2*p + 1], ah1, bh + 2);
                mma_bf16(acc[0][2*p],     ah0, bl);
                mma_bf16(acc[0][2*p + 1], ah0, bl + 2);
                mma_bf16(acc[1][2*p],     ah1, bl);
                mma_bf16(acc[1][2*p + 1], ah1, bl + 2);
                mma_bf16(acc[0][2*p],     al0, bh);
                mma_bf16(acc[0][2*p + 1], al0, bh + 2);
                mma_bf16(acc[1][2*p],     al1, bh);
                mma_bf16(acc[1][2*p + 1], al1, bh + 2);
            }
        }
    }

#pragma unroll
    for (int mi = 0; mi < 2; mi++)
#pragma unroll
    for (int h = 0; h < 2; h++) {
        int row = m0 + wm * 32 + mi * 16 + grp + h * 8;
        if (row < Mrows) {
#pragma unroll
            for (int ni = 0; ni < 8; ni++) {
                int col = n0 + wn * 64 + ni * 8 + tig * 2;
                float2 v;
                v.x = acc[mi][ni][2*h]     + bias[col];
                v.y = acc[mi][ni][2*h + 1] + bias[col + 1];
                *(float2*)&C[(size_t)row * LDIM + col] = v;
            }
        }
    }
}

// ---------------- row L2-normalize, fused bf16 emit (+ optional recip) -----
__global__ void norm_k(const float* __restrict__ in, float* __restrict__ out,
                       __nv_bfloat16* __restrict__ outh, float* __restrict__ rnorm, int M)
{
    int w = (blockIdx.x * blockDim.x + threadIdx.x) >> 5;
    int lane = threadIdx.x & 31;
    if (w >= M) return;
    const float* r = in + (size_t)w * LDIM;
    float vals[8];
    float s = 0.f;
#pragma unroll
    for (int i = 0; i < 8; i++) { vals[i] = r[lane + 32 * i]; s += vals[i] * vals[i]; }
#pragma unroll
    for (int off = 16; off > 0; off >>= 1)
        s += __shfl_xor_sync(0xFFFFFFFFu, s, off);
    float t = s + 1e-12f;
    float sc = rsqrtf(t);
    sc = sc * (1.5f - 0.5f * t * sc * sc);   // Newton: ~1 ulp
    float* o = out + (size_t)w * LDIM;
    __nv_bfloat16* oh = outh + (size_t)w * LDIM;
#pragma unroll
    for (int i = 0; i < 8; i++) {
        float v = vals[i] * sc;
        o[lane + 32 * i] = v;
        oh[lane + 32 * i] = __float2bfloat16(v);
    }
    if (rnorm && lane == 0) rnorm[w] = 1.0f / sc;
}

// ---------------- K1: MMA scores -> bf16 store + 64-block max --------------
// grid (NTOK/128, VOCP/128). cp.async double-buffer; ldmatrix fragments.
__global__ void __launch_bounds__(256, 2)
score_mma(const __nv_bfloat16* __restrict__ zih, const __nv_bfloat16* __restrict__ zch,
          __nv_bfloat16* __restrict__ scores, __nv_bfloat16* __restrict__ bmax)
{
    __shared__ __align__(16) char smembuf[40960];
    const int tid = threadIdx.x;
    const int w = tid >> 5, lane = tid & 31;
    const int grp = lane >> 2, tig = lane & 3;
    const int wm = w >> 1, wn = w & 1;            // 4 x 2 warp grid
    const int t0 = blockIdx.x * 128;
    const int jc = blockIdx.y * 128;

    const int lrow = tid >> 1;                    // loader row 0..127
    const int eo   = (tid & 1) * 16;

    const uint32_t sm0 = smem_u32(smembuf);
    const uint32_t stA[2] = {sm0,         sm0 + 10240};
    const uint32_t stB[2] = {sm0 + 20480, sm0 + 30720};

    uint32_t offA[2], offB[4];
    {
        int la = lane & 15, ha = lane >> 4;       // A: row sel, k half
#pragma unroll
        for (int mi = 0; mi < 2; mi++)
            offA[mi] = (uint32_t)((wm * 32 + mi * 16 + la) * 80 + ha * 16);
        int rb = ((lane >> 4) & 1) * 8 + (lane & 7);
        int cbb = ((lane >> 3) & 1) * 16;
#pragma unroll
        for (int p = 0; p < 4; p++)
            offB[p] = (uint32_t)((wn * 64 + p * 16 + rb) * 80 + cbb);
    }

    float acc[2][8][4] = {};
    int jrow = jc + lrow;
    const int bsz = (jrow < VOC) ? 16 : 0;        // cp.async zero-fill OOB rows
    const __nv_bfloat16* arow = zih + (size_t)(t0 + lrow) * LDIM + eo;
    const __nv_bfloat16* brow = zch + (size_t)jrow * LDIM + eo;
    const uint32_t ldst = (uint32_t)(lrow * 80 + eo * 2);

    // prologue: async stage 0
    cp16(stA[0] + ldst,      arow,     16);
    cp16(stA[0] + ldst + 16, arow + 8, 16);
    cp16(stB[0] + ldst,      brow,     bsz);
    cp16(stB[0] + ldst + 16, brow + 8, bsz);
    CP_COMMIT();

#pragma unroll
    for (int s = 0; s < 8; s++) {            // 8 stages of 32 k-dims
        CP_WAIT0();
        __syncthreads();
        if (s < 7) {                         // async prefetch next stage
            int ko = (s + 1) * 32;
            uint32_t dA = stA[(s + 1) & 1] + ldst;
            uint32_t dB = stB[(s + 1) & 1] + ldst;
            cp16(dA,      arow + ko,     16);
            cp16(dA + 16, arow + ko + 8, 16);
            cp16(dB,      brow + ko,     bsz);
            cp16(dB + 16, brow + ko + 8, bsz);
            CP_COMMIT();
        }
        const uint32_t sA = stA[s & 1], sB = stB[s & 1];
#pragma unroll
        for (int ks = 0; ks < 2; ks++) {
            unsigned a0[4], a1[4];
            ldsm_x4(sA + offA[0] + ks * 32, a0);
            ldsm_x4(sA + offA[1] + ks * 32, a1);
#pragma unroll
            for (int p = 0; p < 4; p++) {
                unsigned bb[4];
                ldsm_x4(sB + offB[p] + ks * 32, bb);
                mma_bf16(acc[0][2*p],     a0, bb);
                mma_bf16(acc[0][2*p + 1], a0, bb + 2);
                mma_bf16(acc[1][2*p],     a1, bb);
                mma_bf16(acc[1][2*p + 1], a1, bb + 2);
            }
        }
    }

    // ---- epilogue: cvt bf16, store, packed block-max (no syncs needed) ----
    const int colbase = wn * 64 + tig * 2;
#pragma unroll
    for (int mi = 0; mi < 2; mi++)
#pragma unroll
    for (int h = 0; h < 2; h++) {
        int row_l = wm * 32 + mi * 16 + grp + h * 8;
        size_t rowoff = (size_t)(t0 + row_l) * VOCP;
        unsigned p[8];
#pragma unroll
        for (int ni = 0; ni < 8; ni++) {
            float2 f2 = make_float2(acc[mi][ni][2*h], acc[mi][ni][2*h + 1]);
            __nv_bfloat162 bb = __float22bfloat162_rn(f2);   // .x -> low half
            p[ni] = *(unsigned*)&bb;
        }
        if (jc + 128 > VOC) {        // mask tail columns with bf16 -inf
#pragma unroll
            for (int ni = 0; ni < 8; ni++) {
                int j = jc + colbase + ni * 8;
                if (j >= VOC)     p[ni] = (p[ni] & 0xFFFF0000u) | 0x0000FF80u;
                if (j + 1 >= VOC) p[ni] = (p[ni] & 0x0000FFFFu) | 0xFF800000u;
            }
        }
#pragma unroll
        for (int ni = 0; ni < 8; ni++)
            *(unsigned*)(scores + rowoff + jc + colbase + ni * 8) = p[ni];
        // packed max tree over this thread's 16 cols, then across tig quad
        __nv_bfloat162 m = *(__nv_bfloat162*)&p[0];
#pragma unroll
        for (int ni = 1; ni < 8; ni++) m = __hmax2(m, *(__nv_bfloat162*)&p[ni]);
        unsigned mu = *(unsigned*)&m;
        unsigned o1 = __shfl_xor_sync(0xFFFFFFFFu, mu, 1);
        m = __hmax2(m, *(__nv_bfloat162*)&o1);
        mu = *(unsigned*)&m;
        unsigned o2 = __shfl_xor_sync(0xFFFFFFFFu, mu, 2);
        m = __hmax2(m, *(__nv_bfloat162*)&o2);
        if (tig == 0) {
            __nv_bfloat16 ms = __hmax(m.x, m.y);
            bmax[(size_t)(t0 + row_l) * BMAXP + (jc >> 6) + wn] = ms;
        }
    }
}

// ---------------- K2: block select + candidate prune + exact top-4 --------
// one warp per token
__global__ void __launch_bounds__(128)
select_k(const __nv_bfloat16* __restrict__ bmax, const __nv_bfloat16* __restrict__ scores,
         const float* __restrict__ zi, const float* __restrict__ zc)
{
    __shared__ int scand[4][NCAND];
    const int wl = threadIdx.x >> 5;
    const int t = (blockIdx.x * blockDim.x + threadIdx.x) >> 5;
    const int lane = threadIdx.x & 31;
    if (t >= NTOK) return;

    // Phase A: lane-local top-8 of 786 blockmaxes
    float lv[8]; int lb[8];
#pragma unroll
    for (int k = 0; k < 8; k++) { lv[k] = -FLT_MAX; lb[k] = INT_MAX; }
    const __nv_bfloat16* bm = bmax + (size_t)t * BMAXP;
#pragma unroll
    for (int k = 0; k < 25; k++) {
        int b = lane + 32 * k;
        if (b < NBLK) {
            float v = __bfloat162float(bm[b]);
            if (v >= lv[7]) insK<8>(v, b, lv, lb);
        }
    }
    // extract top-16 blocks (warp-wide argmax, owner pops)
    int blk[16];
#pragma unroll
    for (int r = 0; r < 16; r++) {
        float cv = lv[0]; int cb = lb[0];
#pragma unroll
        for (int off = 16; off > 0; off >>= 1) {
            float ov = __shfl_xor_sync(0xFFFFFFFFu, cv, off);
            int   ob = __shfl_xor_sync(0xFFFFFFFFu, cb, off);
            if (better(ov, ob, cv, cb)) { cv = ov; cb = ob; }
        }
        blk[r] = cb;
        if (lb[0] == cb) {
#pragma unroll
            for (int k = 0; k < 7; k++) { lv[k] = lv[k+1]; lb[k] = lb[k+1]; }
            lv[7] = -FLT_MAX; lb[7] = INT_MAX;
        }
    }

    // Phase B: lane-local top-12 over the 16 blocks' 1024 bf16 scores
    float cv12[12]; int ci12[12];
#pragma unroll
    for (int k = 0; k < 12; k++) { cv12[k] = -FLT_MAX; ci12[k] = INT_MAX; }
    const __nv_bfloat16* srow = scores + (size_t)t * VOCP;
#pragma unroll
    for (int r = 0; r < 16; r++) {
        int j0 = blk[r] * 64 + lane * 2;
        unsigned u = *(const unsigned*)(srow + j0);
        __nv_bfloat162 b2 = *(__nv_bfloat162*)&u;
        float f0 = __bfloat162float(b2.x);
        float f1 = __bfloat162float(b2.y);
        if (f0 >= cv12[11]) insK<12>(f0, j0,     cv12, ci12);
        if (f1 >= cv12[11]) insK<12>(f1, j0 + 1, cv12, ci12);
    }
    // Phase C: extract top-24 candidates into smem
#pragma unroll
    for (int r = 0; r < NCAND; r++) {
        float cv = cv12[0]; int cb = ci12[0];
#pragma unroll
        for (int off = 16; off > 0; off >>= 1) {
            float ov = __shfl_xor_sync(0xFFFFFFFFu, cv, off);
            int   ob = __shfl_xor_sync(0xFFFFFFFFu, cb, off);
            if (better(ov, ob, cv, cb)) { cv = ov; cb = ob; }
        }
        if (lane == 0) scand[wl][r] = cb;
        if (ci12[0] == cb) {
#pragma unroll
            for (int k = 0; k < 11; k++) { cv12[k] = cv12[k+1]; ci12[k] = ci12[k+1]; }
            cv12[11] = -FLT_MAX; ci12[11] = INT_MAX;
        }
    }
    __syncwarp();

    // Phase D: exact fp32 rescore of 24 candidates -> top-4 + histogram
    const float* zr = zi + (size_t)t * LDIM;
    float a[8];
#pragma unroll
    for (int i = 0; i < 8; i++) a[i] = zr[lane + 32 * i];
    float tv[4] = {-FLT_MAX, -FLT_MAX, -FLT_MAX, -FLT_MAX};
    int   ti[4] = {INT_MAX, INT_MAX, INT_MAX, INT_MAX};
    for (int c = 0; c < NCAND; c += 2) {
        int j0c = scand[wl][c], j1c = scand[wl][c + 1];
        const float* b0 = zc + (size_t)j0c * LDIM;
        const float* b1 = zc + (size_t)j1c * LDIM;
        float s0 = 0.f, s1 = 0.f;
#pragma unroll
        for (int i = 0; i < 8; i++) {
            s0 += a[i] * b0[lane + 32 * i];
            s1 += a[i] * b1[lane + 32 * i];
        }
#pragma unroll
        for (int off = 16; off > 0; off >>= 1) {
            s0 += __shfl_xor_sync(0xFFFFFFFFu, s0, off);
            s1 += __shfl_xor_sync(0xFFFFFFFFu, s1, off);
        }
        insK<4>(s0, j0c, tv, ti);
        insK<4>(s1, j1c, tv, ti);
    }
    if (lane == 0) {
#pragma unroll
        for (int k = 0; k < 4; k++) {
            g_idx[t * 4 + k] = ti[k];
            atomicAdd(&g_counts[ti[k]], 1);
        }
    }
}

// ---------------- quantize + STE out + mse1 --------------------------------
__global__ void quant_k(const float* __restrict__ x, const float* __restrict__ cb,
                        float* __restrict__ out)
{
    int w = (blockIdx.x * blockDim.x + threadIdx.x) >> 5;   // token
    int lane = threadIdx.x & 31;
    if (w >= NTOK) return;
    const float* c0 = cb + (size_t)g_idx[w * 4 + 0] * DDIM;
    const float* c1 = cb + (size_t)g_idx[w * 4 + 1] * DDIM;
    const float* c2 = cb + (size_t)g_idx[w * 4 + 2] * DDIM;
    const float* c3 = cb + (size_t)g_idx[w * 4 + 3] * DDIM;
    double s = 0.0;
    for (int c = lane; c < DDIM; c += 32) {
        float qv = (((c0[c] + c1[c]) + c2[c]) + c3[c]) * 0.25f;
        float xv = x[(size_t)w * DDIM + c];
        float d = qv - xv;
        out[(size_t)w * DDIM + c] = xv + d;     // x + (q - x), matches STE
        s += (double)d * (double)d;
    }
#pragma unroll
    for (int off = 16; off > 0; off >>= 1)
        s += __shfl_down_sync(0xFFFFFFFFu, s, off);
    if (lane == 0) atomicAdd(&g_mse1, s);
}

// ---------------- mse2 via zc reuse: q@Wc+b == mean_k zc_pre[j_k] ----------
__global__ void mse2_k(const float* __restrict__ zc, const float* __restrict__ rn,
                       const float* __restrict__ zi_pre)
{
    int t = (blockIdx.x * blockDim.x + threadIdx.x) >> 5;
    int lane = threadIdx.x & 31;
    if (t >= NTOK) return;
    int j0 = g_idx[t * 4 + 0], j1 = g_idx[t * 4 + 1];
    int j2 = g_idx[t * 4 + 2], j3 = g_idx[t * 4 + 3];
    float w0 = 0.25f * rn[j0], w1 = 0.25f * rn[j1];
    float w2 = 0.25f * rn[j2], w3 = 0.25f * rn[j3];
    const float* z0 = zc + (size_t)j0 * LDIM;
    const float* z1 = zc + (size_t)j1 * LDIM;
    const float* z2 = zc + (size_t)j2 * LDIM;
    const float* z3 = zc + (size_t)j3 * LDIM;
    const float* rp = zi_pre + (size_t)t * LDIM;
    double s = 0.0;
#pragma unroll
    for (int i = 0; i < 8; i++) {
        int c = lane + 32 * i;
        float v = z0[c] * w0 + z1[c] * w1 + z2[c] * w2 + z3[c] * w3 - rp[c];
        s += (double)v * (double)v;
    }
#pragma unroll
    for (int off = 16; off > 0; off >>= 1)
        s += __shfl_down_sync(0xFFFFFFFFu, s, off);
    if (lane == 0) atomicAdd(&g_mse2, s);
}

// ---------------- entropy / usage ------------------------------------------
__global__ void ent_k()
{
    int i0 = blockIdx.x * blockDim.x + threadIdx.x;
    double e = 0.0; int nz = 0;
    for (int i = i0; i < VOC; i += gridDim.x * blockDim.x) {
        int c = g_counts[i];
        if (c > 0) {
            float p = (float)c * (1.0f / (NTOK * KSEL));
            e += (double)(p * logf(p + 1e-10f));
            nz++;
        }
    }
#pragma unroll
    for (int off = 16; off > 0; off >>= 1) {
        e  += __shfl_down_sync(0xFFFFFFFFu, e, off);
        nz += __shfl_down_sync(0xFFFFFFFFu, nz, off);
    }
    if ((threadIdx.x & 31) == 0) { atomicAdd(&g_ent, e); atomicAdd(&g_nz, nz); }
}

// ---------------- finalize scalars -----------------------------------------
__global__ void fin_k(float* __restrict__ out3)
{
    float lp = (float)(-g_ent);
    float mse1 = (float)(g_mse1 / ((double)NTOK * DDIM));
    float mse2 = (float)(g_mse2 / ((double)NTOK * LDIM));
    float loss = 1.25f * mse1 + 1.25f * mse2 + 0.1f * lp;
    out3[0] = loss;
    out3[1] = expf(lp);
    out3[2] = (float)g_nz / (float)VOC / (float)KSEL;
}

// ---------------- launch ----------------------------------------------------
static float* sym_f(const void* s) { void* p = nullptr; cudaGetSymbolAddress(&p, s); return (float*)p; }
static __nv_bfloat16* sym_b(const void* s) { void* p = nullptr; cudaGetSymbolAddress(&p, s); return (__nv_bfloat16*)p; }

#define PROJ_SMEM 81920

extern "C" void kernel_launch(void* const* d_in, const int* in_sizes, int n_in,
                              void* d_out, int out_size)
{
    const float* x  = (const float*)d_in[0];
    const float* cb = (const float*)d_in[1];
    const float* Wi = (const float*)d_in[2];
    const float* bi = (const float*)d_in[3];
    const float* Wc = (const float*)d_in[4];
    const float* bc = (const float*)d_in[5];
    float* out = (float*)d_out;

    float* zi_pre = sym_f(g_zi_pre);
    float* zi     = sym_f(g_zi);
    float* zc     = sym_f(g_zc);
    float* zcn    = sym_f(g_zcn);
    __nv_bfloat16* zih = sym_b(g_zih);
    __nv_bfloat16* zch = sym_b(g_zch);
    __nv_bfloat16* cbh = sym_b(g_cbh);
    __nv_bfloat16* cbl = sym_b(g_cbl);
    __nv_bfloat16* xh  = sym_b(g_xh);
    __nv_bfloat16* xl  = sym_b(g_xl);
    __nv_bfloat16* wth = sym_b(g_wth);
    __nv_bfloat16* wtl = sym_b(g_wtl);
    __nv_bfloat16* wih = sym_b(g_wih);
    __nv_bfloat16* wil = sym_b(g_wil);
    __nv_bfloat16* scores = sym_b(g_scores);
    __nv_bfloat16* bmax   = sym_b(g_bmax);

    cudaFuncSetAttribute(proj_mma, cudaFuncAttributeMaxDynamicSharedMemorySize, PROJ_SMEM);

    init_k<<<64, 256>>>();
    // bf16 hi/lo splits: codebook, x, W_in^T, W_code^T
    split_k<<<1024, 256>>>((const float4*)cb, (uint2*)cbh, (uint2*)cbl,
                           VOC * DDIM / 4);
    split_k<<<256, 256>>>((const float4*)x, (uint2*)xh, (uint2*)xl,
                          NTOK * DDIM / 4);
    wsplit_k<<<(LDIM * DDIM + 255) / 256, 256>>>(Wi, wih, wil);
    wsplit_k<<<(LDIM * DDIM + 255) / 256, 256>>>(Wc, wth, wtl);
    // zi_pre = x @ W_in + b_in via bf16-split MMA; zi = l2n (+ bf16 copy)
    proj_mma<<<dim3(NTOK / 128, LDIM / 128), 256, PROJ_SMEM>>>(
        xh, xl, wih, wil, bi, zi_pre, NTOK);
    norm_k<<<NTOK / 8, 256>>>(zi_pre, zi, zih, nullptr, NTOK);
    // zc_pre = cb @ W_code + b_code via bf16-split MMA; zc = l2n (+ bf16, recip)
    proj_mma<<<dim3((VOC + 127) / 128, LDIM / 128), 256, PROJ_SMEM>>>(
        cbh, cbl, wth, wtl, bc, zc, VOC);
    norm_k<<<(VOC + 7) / 8, 256>>>(zc, zc, zch, zcn, VOC);
    // K1: bf16 MMA scores (cp.async + ldmatrix) -> gmem + blockmax
    score_mma<<<dim3(NTOK / 128, VOCP / 128), 256>>>(zih, zch, scores, bmax);
    // K2: block-select + prune + exact top-4 + histogram
    select_k<<<NTOK / 4, 128>>>(bmax, scores, zi, zc);
    // quantize + STE output + mse1
    quant_k<<<NTOK / 8, 256>>>(x, cb, out);
    // mse2 without a GEMM: q@Wc+b == mean of selected zc_pre rows
    mse2_k<<<NTOK / 8, 256>>>(zc, zcn, zi_pre);
    ent_k<<<64, 256>>>();
    fin_k<<<1, 1>>>(out + (size_t)NTOK * DDIM);
}

// round 14
// speedup vs baseline: 1.4108x; 1.0545x over previous
#include <cuda_runtime.h>
#include <cuda_bf16.h>
#include <math.h>
#include <float.h>
#include <limits.h>
#include <stdint.h>

// Problem constants
#define NTOK 4096      // B*S
#define DDIM 768
#define LDIM 256
#define VOC  50265
#define VOCP 50304     // 393 tiles of 128
#define NBLK 786       // 64-code blocks (VOCP/64)
#define BMAXP 788      // padded row
#define KSEL 4
#define NCAND 24
#define ZC_BLKS 393    // ceil(VOC/128)
#define ZI_BLKS 32     // NTOK/128

// ---------------- scratch (device globals; no allocations) ----------------
__device__ float  g_zi_pre[NTOK * LDIM];      // x@W_in+b (kept for mse2 ref)
__device__ float  g_zi[NTOK * LDIM];          // normalized
__device__ float  g_zc[VOC * LDIM];           // normalized latent codebook
__device__ float  g_zcn[VOC];                 // reciprocal norm: zc_pre = zc * g_zcn
__device__ __nv_bfloat16 g_zih[NTOK * LDIM];
__device__ __nv_bfloat16 g_zch[VOC * LDIM];
__device__ __nv_bfloat16 g_cbh[VOC * DDIM];   // bf16 hi split of codebook
__device__ __nv_bfloat16 g_cbl[VOC * DDIM];   // bf16 lo split of codebook
__device__ __nv_bfloat16 g_xh[NTOK * DDIM];   // bf16 hi split of x
__device__ __nv_bfloat16 g_xl[NTOK * DDIM];   // bf16 lo split of x
__device__ __nv_bfloat16 g_wth[LDIM * DDIM];  // W_code^T hi (n-major, k-contig)
__device__ __nv_bfloat16 g_wtl[LDIM * DDIM];  // W_code^T lo
__device__ __nv_bfloat16 g_wih[LDIM * DDIM];  // W_in^T hi
__device__ __nv_bfloat16 g_wil[LDIM * DDIM];  // W_in^T lo
__device__ __nv_bfloat16 g_scores[(size_t)NTOK * VOCP];   // all approx scores
__device__ __nv_bfloat16 g_bmax[(size_t)NTOK * BMAXP];    // per-64-block max
__device__ int    g_idx[NTOK * KSEL];
__device__ int    g_counts[VOC];
__device__ double g_mse1, g_mse2, g_ent;
__device__ int    g_nz;

// ---------------- helpers ----------------
__device__ __forceinline__ uint32_t smem_u32(const void* p) {
    uint32_t a;
    asm("{ .reg .u64 t; cvta.to.shared.u64 t, %1; cvt.u32.u64 %0, t; }" : "=r"(a) : "l"(p));
    return a;
}
__device__ __forceinline__ bool better(float v, int j, float v2, int j2) {
    return (v > v2) || (v == v2 && j < j2);
}
template <int K>
__device__ __forceinline__ void insK(float v, int j, float tv[K], int ti[K]) {
    if (!better(v, j, tv[K-1], ti[K-1])) return;
    tv[K-1] = v; ti[K-1] = j;
#pragma unroll
    for (int k = K-1; k > 0; k--) {
        if (better(tv[k], ti[k], tv[k-1], ti[k-1])) {
            float fv = tv[k]; tv[k] = tv[k-1]; tv[k-1] = fv;
            int   fi = ti[k]; ti[k] = ti[k-1]; ti[k-1] = fi;
        }
    }
}

// ---------------- bf16 mma + ldmatrix + cp.async helpers ----------------
__device__ __forceinline__ void mma_bf16(float d[4], const unsigned a[4], const unsigned b[2]) {
    asm("mma.sync.aligned.m16n8k16.row.col.f32.bf16.bf16.f32 "
        "{%0,%1,%2,%3},{%4,%5,%6,%7},{%8,%9},{%0,%1,%2,%3};"
        : "+f"(d[0]), "+f"(d[1]), "+f"(d[2]), "+f"(d[3])
        : "r"(a[0]), "r"(a[1]), "r"(a[2]), "r"(a[3]), "r"(b[0]), "r"(b[1]));
}
__device__ __forceinline__ void ldsm_x4(uint32_t addr, unsigned r[4]) {
    asm volatile("ldmatrix.sync.aligned.m8n8.x4.shared.b16 {%0,%1,%2,%3}, [%4];"
        : "=r"(r[0]), "=r"(r[1]), "=r"(r[2]), "=r"(r[3]) : "r"(addr));
}
__device__ __forceinline__ void cp16(uint32_t dst, const void* src, int ssz) {
    asm volatile("cp.async.cg.shared.global [%0], [%1], 16, %2;"
        :: "r"(dst), "l"(src), "r"(ssz) : "memory");
}
#define CP_COMMIT() asm volatile("cp.async.commit_group;" ::: "memory")
#define CP_WAIT0()  asm volatile("cp.async.wait_group 0;" ::: "memory")

// ---------------- init ----------------
__global__ void init_k() {
    int i = blockIdx.x * blockDim.x + threadIdx.x;
    for (int v = i; v < VOC; v += gridDim.x * blockDim.x) g_counts[v] = 0;
    if (i == 0) { g_mse1 = 0.0; g_mse2 = 0.0; g_ent = 0.0; g_nz = 0; }
}

// ---------------- fused split kernel: cb, x (streaming) + Wi, Wc (transpose)
// block ranges: [0,1024) cb-split, [1024,1152) x-split,
//               [1152,1216) Wi T-split, [1216,1280) Wc T-split
__device__ __forceinline__ void split_stream(const float4* in, uint2* oh, uint2* ol,
                                             int n4, int bid, int nblk)
{
    int i = bid * blockDim.x + threadIdx.x;
    int stride = nblk * blockDim.x;
    for (; i < n4; i += stride) {
        float4 v = in[i];
        __nv_bfloat16 h0 = __float2bfloat16(v.x);
        __nv_bfloat16 h1 = __float2bfloat16(v.y);
        __nv_bfloat16 h2 = __float2bfloat16(v.z);
        __nv_bfloat16 h3 = __float2bfloat16(v.w);
        __nv_bfloat16 l0 = __float2bfloat16(v.x - __bfloat162float(h0));
        __nv_bfloat16 l1 = __float2bfloat16(v.y - __bfloat162float(h1));
        __nv_bfloat16 l2 = __float2bfloat16(v.z - __bfloat162float(h2));
        __nv_bfloat16 l3 = __float2bfloat16(v.w - __bfloat162float(h3));
        __nv_bfloat162 hp0 = {h0, h1}, hp1 = {h2, h3};
        __nv_bfloat162 lp0 = {l0, l1}, lp1 = {l2, l3};
        uint2 uh, ul;
        uh.x = *(unsigned*)&hp0; uh.y = *(unsigned*)&hp1;
        ul.x = *(unsigned*)&lp0; ul.y = *(unsigned*)&lp1;
        oh[i] = uh; ol[i] = ul;
    }
}
__device__ __forceinline__ void split_transpose(const float* W, __nv_bfloat16* wh,
                                                __nv_bfloat16* wl, int bid, int nblk)
{
    int i = bid * blockDim.x + threadIdx.x;
    int stride = nblk * blockDim.x;
    for (; i < LDIM * DDIM; i += stride) {
        int n = i / DDIM, k = i - n * DDIM;
        float v = W[k * LDIM + n];
        __nv_bfloat16 h = __float2bfloat16(v);
        wh[i] = h;
        wl[i] = __float2bfloat16(v - __bfloat162float(h));
    }
}
__global__ void fsplit_k(const float* __restrict__ cb, const float* __restrict__ x,
                         const float* __restrict__ Wi, const float* __restrict__ Wc)
{
    int b = blockIdx.x;
    if (b < 1024)
        split_stream((const float4*)cb, (uint2*)g_cbh, (uint2*)g_cbl,
                     VOC * DDIM / 4, b, 1024);
    else if (b < 1152)
        split_stream((const float4*)x, (uint2*)g_xh, (uint2*)g_xl,
                     NTOK * DDIM / 4, b - 1024, 128);
    else if (b < 1216)
        split_transpose(Wi, g_wih, g_wil, b - 1152, 64);
    else
        split_transpose(Wc, g_wth, g_wtl, b - 1216, 64);
}

// ---------------- merged projection GEMM (zc + zi in one launch) -----------
// blocks [0,393): zc rows (cb @ Wc + bc); blocks [393,425): zi rows (x @ Wi + bi)
// 3-product bf16-split MMA, K=768 in 24 double-buffered 32-k stages.
__global__ void __launch_bounds__(256, 2)
proj_mma(const float* __restrict__ bc, const float* __restrict__ bi)
{
    extern __shared__ __align__(16) char dynbuf[];
    const int tid = threadIdx.x;
    const int w = tid >> 5, lane = tid & 31;
    const int grp = lane >> 2, tig = lane & 3;
    const int wm = w >> 1, wn = w & 1;            // 4 x 2 warp grid
    const int bx = blockIdx.x;
    const __nv_bfloat16 *ah_g, *al_g, *bh_g, *bl_g;
    const float* bias;
    float* C;
    int Mrows, m0;
    if (bx < ZC_BLKS) {
        ah_g = g_cbh; al_g = g_cbl; bh_g = g_wth; bl_g = g_wtl;
        bias = bc; C = g_zc; Mrows = VOC; m0 = bx * 128;
    } else {
        ah_g = g_xh; al_g = g_xl; bh_g = g_wih; bl_g = g_wil;
        bias = bi; C = g_zi_pre; Mrows = NTOK; m0 = (bx - ZC_BLKS) * 128;
    }
    const int n0 = blockIdx.y * 128;
    const int lrow = tid >> 1;                    // loader row 0..127
    const int eo   = (tid & 1) * 16;

    const uint32_t sm0 = smem_u32(dynbuf);
    const uint32_t ldst = (uint32_t)(lrow * 80 + eo * 2);

    uint32_t offA[2], offB[4];
    {
        int la = lane & 15, ha = lane >> 4;
#pragma unroll
        for (int mi = 0; mi < 2; mi++)
            offA[mi] = (uint32_t)((wm * 32 + mi * 16 + la) * 80 + ha * 16);
        int rb = ((lane >> 4) & 1) * 8 + (lane & 7);
        int cbb = ((lane >> 3) & 1) * 16;
#pragma unroll
        for (int p = 0; p < 4; p++)
            offB[p] = (uint32_t)((wn * 64 + p * 16 + rb) * 80 + cbb);
    }

    float acc[2][8][4] = {};
    const int asz = (m0 + lrow < Mrows) ? 16 : 0; // zero-fill OOB rows
    const __nv_bfloat16* ah_src = ah_g + (size_t)(m0 + lrow) * DDIM + eo;
    const __nv_bfloat16* al_src = al_g + (size_t)(m0 + lrow) * DDIM + eo;
    const __nv_bfloat16* bh_src = bh_g + (size_t)(n0 + lrow) * DDIM + eo;
    const __nv_bfloat16* bl_src = bl_g + (size_t)(n0 + lrow) * DDIM + eo;

    {
        uint32_t b = sm0;
        cp16(b + ldst,              ah_src,     asz);
        cp16(b + ldst + 16,         ah_src + 8, asz);
        cp16(b + 10240 + ldst,      al_src,     asz);
        cp16(b + 10240 + ldst + 16, al_src + 8, asz);
        cp16(b + 20480 + ldst,      bh_src,     16);
        cp16(b + 20480 + ldst + 16, bh_src + 8, 16);
        cp16(b + 30720 + ldst,      bl_src,     16);
        cp16(b + 30720 + ldst + 16, bl_src + 8, 16);
        CP_COMMIT();
    }

    for (int s = 0; s < 24; s++) {           // 24 stages of 32 k-dims
        CP_WAIT0();
        __syncthreads();
        if (s < 23) {
            int ko = (s + 1) * 32;
            uint32_t b = sm0 + (uint32_t)(((s + 1) & 1) * 40960);
            cp16(b + ldst,              ah_src + ko,     asz);
            cp16(b + ldst + 16,         ah_src + ko + 8, asz);
            cp16(b + 10240 + ldst,      al_src + ko,     asz);
            cp16(b + 10240 + ldst + 16, al_src + ko + 8, asz);
            cp16(b + 20480 + ldst,      bh_src + ko,     16);
            cp16(b + 20480 + ldst + 16, bh_src + ko + 8, 16);
            cp16(b + 30720 + ldst,      bl_src + ko,     16);
            cp16(b + 30720 + ldst + 16, bl_src + ko + 8, 16);
            CP_COMMIT();
        }
        uint32_t bb_ = sm0 + (uint32_t)((s & 1) * 40960);
        uint32_t sAh = bb_, sAl = bb_ + 10240, sBh = bb_ + 20480, sBl = bb_ + 30720;
#pragma unroll
        for (int ks = 0; ks < 2; ks++) {
            unsigned ah0[4], ah1[4], al0[4], al1[4];
            ldsm_x4(sAh + offA[0] + ks * 32, ah0);
            ldsm_x4(sAh + offA[1] + ks * 32, ah1);
            ldsm_x4(sAl + offA[0] + ks * 32, al0);
            ldsm_x4(sAl + offA[1] + ks * 32, al1);
#pragma unroll
            for (int p = 0; p < 4; p++) {
                unsigned bh[4], bl[4];
                ldsm_x4(sBh + offB[p] + ks * 32, bh);
                ldsm_x4(sBl + offB[p] + ks * 32, bl);
                mma_bf16(acc[0][2*p],     ah0, bh);
                mma_bf16(acc[0][2*p + 1], ah0, bh + 2);
                mma_bf16(acc[1][2*p],     ah1, bh);
                mma_bf16(acc[1][2*p + 1], ah1, bh + 2);
                mma_bf16(acc[0][2*p],     ah0, bl);
                mma_bf16(acc[0][2*p + 1], ah0, bl + 2);
                mma_bf16(acc[1][2*p],     ah1, bl);
                mma_bf16(acc[1][2*p + 1], ah1, bl + 2);
                mma_bf16(acc[0][2*p],     al0, bh);
                mma_bf16(acc[0][2*p + 1], al0, bh + 2);
                mma_bf16(acc[1][2*p],     al1, bh);
                mma_bf16(acc[1][2*p + 1], al1, bh + 2);
            }
        }
    }

#pragma unroll
    for (int mi = 0; mi < 2; mi++)
#pragma unroll
    for (int h = 0; h < 2; h++) {
        int row = m0 + wm * 32 + mi * 16 + grp + h * 8;
        if (row < Mrows) {
#pragma unroll
            for (int ni = 0; ni < 8; ni++) {
                int col = n0 + wn * 64 + ni * 8 + tig * 2;
                float2 v;
                v.x = acc[mi][ni][2*h]     + bias[col];
                v.y = acc[mi][ni][2*h + 1] + bias[col + 1];
                *(float2*)&C[(size_t)row * LDIM + col] = v;
            }
        }
    }
}

// ---------------- merged row L2-normalize (zi rows then zc rows) -----------
__global__ void norm_k()
{
    int w = (blockIdx.x * blockDim.x + threadIdx.x) >> 5;
    int lane = threadIdx.x & 31;
    if (w >= NTOK + VOC) return;
    const float* in;
    float* out;
    __nv_bfloat16* oh;
    bool zc_path = (w >= NTOK);
    int row = zc_path ? (w - NTOK) : w;
    if (zc_path) { in = g_zc;     out = g_zc; oh = g_zch; }
    else         { in = g_zi_pre; out = g_zi; oh = g_zih; }
    const float* r = in + (size_t)row * LDIM;
    float vals[8];
    float s = 0.f;
#pragma unroll
    for (int i = 0; i < 8; i++) { vals[i] = r[lane + 32 * i]; s += vals[i] * vals[i]; }
#pragma unroll
    for (int off = 16; off > 0; off >>= 1)
        s += __shfl_xor_sync(0xFFFFFFFFu, s, off);
    float t = s + 1e-12f;
    float sc = rsqrtf(t);
    sc = sc * (1.5f - 0.5f * t * sc * sc);   // Newton: ~1 ulp
    float* o = out + (size_t)row * LDIM;
    __nv_bfloat16* ohp = oh + (size_t)row * LDIM;
#pragma unroll
    for (int i = 0; i < 8; i++) {
        float v = vals[i] * sc;
        o[lane + 32 * i] = v;
        ohp[lane + 32 * i] = __float2bfloat16(v);
    }
    if (zc_path && lane == 0) g_zcn[row] = 1.0f / sc;
}

// ---------------- K1: MMA scores -> bf16 store + 64-block max --------------
__global__ void __launch_bounds__(256, 2)
score_mma(const __nv_bfloat16* __restrict__ zih, const __nv_bfloat16* __restrict__ zch,
          __nv_bfloat16* __restrict__ scores, __nv_bfloat16* __restrict__ bmax)
{
    __shared__ __align__(16) char smembuf[40960];
    const int tid = threadIdx.x;
    const int w = tid >> 5, lane = tid & 31;
    const int grp = lane >> 2, tig = lane & 3;
    const int wm = w >> 1, wn = w & 1;            // 4 x 2 warp grid
    const int t0 = blockIdx.x * 128;
    const int jc = blockIdx.y * 128;

    const int lrow = tid >> 1;                    // loader row 0..127
    const int eo   = (tid & 1) * 16;

    const uint32_t sm0 = smem_u32(smembuf);
    const uint32_t stA[2] = {sm0,         sm0 + 10240};
    const uint32_t stB[2] = {sm0 + 20480, sm0 + 30720};

    uint32_t offA[2], offB[4];
    {
        int la = lane & 15, ha = lane >> 4;       // A: row sel, k half
#pragma unroll
        for (int mi = 0; mi < 2; mi++)
            offA[mi] = (uint32_t)((wm * 32 + mi * 16 + la) * 80 + ha * 16);
        int rb = ((lane >> 4) & 1) * 8 + (lane & 7);
        int cbb = ((lane >> 3) & 1) * 16;
#pragma unroll
        for (int p = 0; p < 4; p++)
            offB[p] = (uint32_t)((wn * 64 + p * 16 + rb) * 80 + cbb);
    }

    float acc[2][8][4] = {};
    int jrow = jc + lrow;
    const int bsz = (jrow < VOC) ? 16 : 0;        // cp.async zero-fill OOB rows
    const __nv_bfloat16* arow = zih + (size_t)(t0 + lrow) * LDIM + eo;
    const __nv_bfloat16* brow = zch + (size_t)jrow * LDIM + eo;
    const uint32_t ldst = (uint32_t)(lrow * 80 + eo * 2);

    // prologue: async stage 0
    cp16(stA[0] + ldst,      arow,     16);
    cp16(stA[0] + ldst + 16, arow + 8, 16);
    cp16(stB[0] + ldst,      brow,     bsz);
    cp16(stB[0] + ldst + 16, brow + 8, bsz);
    CP_COMMIT();

#pragma unroll
    for (int s = 0; s < 8; s++) {            // 8 stages of 32 k-dims
        CP_WAIT0();
        __syncthreads();
        if (s < 7) {                         // async prefetch next stage
            int ko = (s + 1) * 32;
            uint32_t dA = stA[(s + 1) & 1] + ldst;
            uint32_t dB = stB[(s + 1) & 1] + ldst;
            cp16(dA,      arow + ko,     16);
            cp16(dA + 16, arow + ko + 8, 16);
            cp16(dB,      brow + ko,     bsz);
            cp16(dB + 16, brow + ko + 8, bsz);
            CP_COMMIT();
        }
        const uint32_t sA = stA[s & 1], sB = stB[s & 1];
#pragma unroll
        for (int ks = 0; ks < 2; ks++) {
            unsigned a0[4], a1[4];
            ldsm_x4(sA + offA[0] + ks * 32, a0);
            ldsm_x4(sA + offA[1] + ks * 32, a1);
#pragma unroll
            for (int p = 0; p < 4; p++) {
                unsigned bb[4];
                ldsm_x4(sB + offB[p] + ks * 32, bb);
                mma_bf16(acc[0][2*p],     a0, bb);
                mma_bf16(acc[0][2*p + 1], a0, bb + 2);
                mma_bf16(acc[1][2*p],     a1, bb);
                mma_bf16(acc[1][2*p + 1], a1, bb + 2);
            }
        }
    }

    // ---- epilogue: cvt bf16, store, packed block-max (no syncs needed) ----
    const int colbase = wn * 64 + tig * 2;
#pragma unroll
    for (int mi = 0; mi < 2; mi++)
#pragma unroll
    for (int h = 0; h < 2; h++) {
        int row_l = wm * 32 + mi * 16 + grp + h * 8;
        size_t rowoff = (size_t)(t0 + row_l) * VOCP;
        unsigned p[8];
#pragma unroll
        for (int ni = 0; ni < 8; ni++) {
            float2 f2 = make_float2(acc[mi][ni][2*h], acc[mi][ni][2*h + 1]);
            __nv_bfloat162 bb = __float22bfloat162_rn(f2);   // .x -> low half
            p[ni] = *(unsigned*)&bb;
        }
        if (jc + 128 > VOC) {        // mask tail columns with bf16 -inf
#pragma unroll
            for (int ni = 0; ni < 8; ni++) {
                int j = jc + colbase + ni * 8;
                if (j >= VOC)     p[ni] = (p[ni] & 0xFFFF0000u) | 0x0000FF80u;
                if (j + 1 >= VOC) p[ni] = (p[ni] & 0x0000FFFFu) | 0xFF800000u;
            }
        }
#pragma unroll
        for (int ni = 0; ni < 8; ni++)
            *(unsigned*)(scores + rowoff + jc + colbase + ni * 8) = p[ni];
        __nv_bfloat162 m = *(__nv_bfloat162*)&p[0];
#pragma unroll
        for (int ni = 1; ni < 8; ni++) m = __hmax2(m, *(__nv_bfloat162*)&p[ni]);
        unsigned mu = *(unsigned*)&m;
        unsigned o1 = __shfl_xor_sync(0xFFFFFFFFu, mu, 1);
        m = __hmax2(m, *(__nv_bfloat162*)&o1);
        mu = *(unsigned*)&m;
        unsigned o2 = __shfl_xor_sync(0xFFFFFFFFu, mu, 2);
        m = __hmax2(m, *(__nv_bfloat162*)&o2);
        if (tig == 0) {
            __nv_bfloat16 ms = __hmax(m.x, m.y);
            bmax[(size_t)(t0 + row_l) * BMAXP + (jc >> 6) + wn] = ms;
        }
    }
}

// ---------------- K2: block select + candidate prune + exact top-4 --------
__global__ void __launch_bounds__(128)
select_k(const __nv_bfloat16* __restrict__ bmax, const __nv_bfloat16* __restrict__ scores,
         const float* __restrict__ zi, const float* __restrict__ zc)
{
    __shared__ int scand[4][NCAND];
    const int wl = threadIdx.x >> 5;
    const int t = (blockIdx.x * blockDim.x + threadIdx.x) >> 5;
    const int lane = threadIdx.x & 31;
    if (t >= NTOK) return;

    // Phase A: lane-local top-8 of 786 blockmaxes
    float lv[8]; int lb[8];
#pragma unroll
    for (int k = 0; k < 8; k++) { lv[k] = -FLT_MAX; lb[k] = INT_MAX; }
    const __nv_bfloat16* bm = bmax + (size_t)t * BMAXP;
#pragma unroll
    for (int k = 0; k < 25; k++) {
        int b = lane + 32 * k;
        if (b < NBLK) {
            float v = __bfloat162float(bm[b]);
            if (v >= lv[7]) insK<8>(v, b, lv, lb);
        }
    }
    // extract top-16 blocks (warp-wide argmax, owner pops)
    int blk[16];
#pragma unroll
    for (int r = 0; r < 16; r++) {
        float cv = lv[0]; int cb = lb[0];
#pragma unroll
        for (int off = 16; off > 0; off >>= 1) {
            float ov = __shfl_xor_sync(0xFFFFFFFFu, cv, off);
            int   ob = __shfl_xor_sync(0xFFFFFFFFu, cb, off);
            if (better(ov, ob, cv, cb)) { cv = ov; cb = ob; }
        }
        blk[r] = cb;
        if (lb[0] == cb) {
#pragma unroll
            for (int k = 0; k < 7; k++) { lv[k] = lv[k+1]; lb[k] = lb[k+1]; }
            lv[7] = -FLT_MAX; lb[7] = INT_MAX;
        }
    }

    // Phase B: lane-local top-12 over the 16 blocks' 1024 bf16 scores
    float cv12[12]; int ci12[12];
#pragma unroll
    for (int k = 0; k < 12; k++) { cv12[k] = -FLT_MAX; ci12[k] = INT_MAX; }
    const __nv_bfloat16* srow = scores + (size_t)t * VOCP;
#pragma unroll
    for (int r = 0; r < 16; r++) {
        int j0 = blk[r] * 64 + lane * 2;
        unsigned u = *(const unsigned*)(srow + j0);
        __nv_bfloat162 b2 = *(__nv_bfloat162*)&u;
        float f0 = __bfloat162float(b2.x);
        float f1 = __bfloat162float(b2.y);
        if (f0 >= cv12[11]) insK<12>(f0, j0,     cv12, ci12);
        if (f1 >= cv12[11]) insK<12>(f1, j0 + 1, cv12, ci12);
    }
    // Phase C: extract top-24 candidates into smem
#pragma unroll
    for (int r = 0; r < NCAND; r++) {
        float cv = cv12[0]; int cb = ci12[0];
#pragma unroll
        for (int off = 16; off > 0; off >>= 1) {
            float ov = __shfl_xor_sync(0xFFFFFFFFu, cv, off);
            int   ob = __shfl_xor_sync(0xFFFFFFFFu, cb, off);
            if (better(ov, ob, cv, cb)) { cv = ov; cb = ob; }
        }
        if (lane == 0) scand[wl][r] = cb;
        if (ci12[0] == cb) {
#pragma unroll
            for (int k = 0; k < 11; k++) { cv12[k] = cv12[k+1]; ci12[k] = ci12[k+1]; }
            cv12[11] = -FLT_MAX; ci12[11] = INT_MAX;
        }
    }
    __syncwarp();

    // Phase D: exact fp32 rescore of 24 candidates -> top-4 + histogram
    const float* zr = zi + (size_t)t * LDIM;
    float a[8];
#pragma unroll
    for (int i = 0; i < 8; i++) a[i] = zr[lane + 32 * i];
    float tv[4] = {-FLT_MAX, -FLT_MAX, -FLT_MAX, -FLT_MAX};
    int   ti[4] = {INT_MAX, INT_MAX, INT_MAX, INT_MAX};
    for (int c = 0; c < NCAND; c += 2) {
        int j0c = scand[wl][c], j1c = scand[wl][c + 1];
        const float* b0 = zc + (size_t)j0c * LDIM;
        const float* b1 = zc + (size_t)j1c * LDIM;
        float s0 = 0.f, s1 = 0.f;
#pragma unroll
        for (int i = 0; i < 8; i++) {
            s0 += a[i] * b0[lane + 32 * i];
            s1 += a[i] * b1[lane + 32 * i];
        }
#pragma unroll
        for (int off = 16; off > 0; off >>= 1) {
            s0 += __shfl_xor_sync(0xFFFFFFFFu, s0, off);
            s1 += __shfl_xor_sync(0xFFFFFFFFu, s1, off);
        }
        insK<4>(s0, j0c, tv, ti);
        insK<4>(s1, j1c, tv, ti);
    }
    if (lane == 0) {
#pragma unroll
        for (int k = 0; k < 4; k++) {
            g_idx[t * 4 + k] = ti[k];
            atomicAdd(&g_counts[ti[k]], 1);
        }
    }
}

// ---------------- fused tail: quantize + STE out + mse1 + mse2 -------------
__global__ void tail_k(const float* __restrict__ x, const float* __restrict__ cb,
                       float* __restrict__ out, const float* __restrict__ zc,
                       const float* __restrict__ rn, const float* __restrict__ zi_pre)
{
    int w = (blockIdx.x * blockDim.x + threadIdx.x) >> 5;   // token
    int lane = threadIdx.x & 31;
    if (w >= NTOK) return;
    int j0 = g_idx[w * 4 + 0], j1 = g_idx[w * 4 + 1];
    int j2 = g_idx[w * 4 + 2], j3 = g_idx[w * 4 + 3];
    // quant + STE + mse1 over DDIM
    const float* c0 = cb + (size_t)j0 * DDIM;
    const float* c1 = cb + (size_t)j1 * DDIM;
    const float* c2 = cb + (size_t)j2 * DDIM;
    const float* c3 = cb + (size_t)j3 * DDIM;
    double s = 0.0;
    for (int c = lane; c < DDIM; c += 32) {
        float qv = (((c0[c] + c1[c]) + c2[c]) + c3[c]) * 0.25f;
        float xv = x[(size_t)w * DDIM + c];
        float d = qv - xv;
        out[(size_t)w * DDIM + c] = xv + d;     // x + (q - x), matches STE
        s += (double)d * (double)d;
    }
    // mse2 over LDIM: q@Wc+b == mean of selected zc_pre rows
    float w0 = 0.25f * rn[j0], w1 = 0.25f * rn[j1];
    float w2 = 0.25f * rn[j2], w3 = 0.25f * rn[j3];
    const float* z0 = zc + (size_t)j0 * LDIM;
    const float* z1 = zc + (size_t)j1 * LDIM;
    const float* z2 = zc + (size_t)j2 * LDIM;
    const float* z3 = zc + (size_t)j3 * LDIM;
    const float* rp = zi_pre + (size_t)w * LDIM;
    double s2 = 0.0;
#pragma unroll
    for (int i = 0; i < 8; i++) {
        int c = lane + 32 * i;
        float v = z0[c] * w0 + z1[c] * w1 + z2[c] * w2 + z3[c] * w3 - rp[c];
        s2 += (double)v * (double)v;
    }
#pragma unroll
    for (int off = 16; off > 0; off >>= 1) {
        s  += __shfl_down_sync(0xFFFFFFFFu, s, off);
        s2 += __shfl_down_sync(0xFFFFFFFFu, s2, off);
    }
    if (lane == 0) { atomicAdd(&g_mse1, s); atomicAdd(&g_mse2, s2); }
}

// ---------------- entropy / usage ------------------------------------------
__global__ void ent_k()
{
    int i0 = blockIdx.x * blockDim.x + threadIdx.x;
    double e = 0.0; int nz = 0;
    for (int i = i0; i < VOC; i += gridDim.x * blockDim.x) {
        int c = g_counts[i];
        if (c > 0) {
            float p = (float)c * (1.0f / (NTOK * KSEL));
            e += (double)(p * logf(p + 1e-10f));
            nz++;
        }
    }
#pragma unroll
    for (int off = 16; off > 0; off >>= 1) {
        e  += __shfl_down_sync(0xFFFFFFFFu, e, off);
        nz += __shfl_down_sync(0xFFFFFFFFu, nz, off);
    }
    if ((threadIdx.x & 31) == 0) { atomicAdd(&g_ent, e); atomicAdd(&g_nz, nz); }
}

// ---------------- finalize scalars -----------------------------------------
__global__ void fin_k(float* __restrict__ out3)
{
    float lp = (float)(-g_ent);
    float mse1 = (float)(g_mse1 / ((double)NTOK * DDIM));
    float mse2 = (float)(g_mse2 / ((double)NTOK * LDIM));
    float loss = 1.25f * mse1 + 1.25f * mse2 + 0.1f * lp;
    out3[0] = loss;
    out3[1] = expf(lp);
    out3[2] = (float)g_nz / (float)VOC / (float)KSEL;
}

// ---------------- launch ----------------------------------------------------
static float* sym_f(const void* s) { void* p = nullptr; cudaGetSymbolAddress(&p, s); return (float*)p; }
static __nv_bfloat16* sym_b(const void* s) { void* p = nullptr; cudaGetSymbolAddress(&p, s); return (__nv_bfloat16*)p; }

#define PROJ_SMEM 81920

extern "C" void kernel_launch(void* const* d_in, const int* in_sizes, int n_in,
                              void* d_out, int out_size)
{
    const float* x  = (const float*)d_in[0];
    const float* cb = (const float*)d_in[1];
    const float* Wi = (const float*)d_in[2];
    const float* bi = (const float*)d_in[3];
    const float* Wc = (const float*)d_in[4];
    const float* bc = (const float*)d_in[5];
    float* out = (float*)d_out;

    float* zi_pre = sym_f(g_zi_pre);
    float* zi     = sym_f(g_zi);
    float* zc     = sym_f(g_zc);
    float* zcn    = sym_f(g_zcn);
    __nv_bfloat16* zih = sym_b(g_zih);
    __nv_bfloat16* zch = sym_b(g_zch);
    __nv_bfloat16* scores = sym_b(g_scores);
    __nv_bfloat16* bmax   = sym_b(g_bmax);

    cudaFuncSetAttribute(proj_mma, cudaFuncAttributeMaxDynamicSharedMemorySize, PROJ_SMEM);

    init_k<<<64, 256>>>();
    // fused bf16 hi/lo splits: cb, x (stream) + Wi, Wc (transpose)
    fsplit_k<<<1280, 256>>>(cb, x, Wi, Wc);
    // merged projections: zc_pre (blocks<393) + zi_pre (blocks>=393)
    proj_mma<<<dim3(ZC_BLKS + ZI_BLKS, LDIM / 128), 256, PROJ_SMEM>>>(bc, bi);
    // merged normalize: zi rows then zc rows (+ bf16 copies, zc recip norms)
    norm_k<<<(NTOK + VOC + 7) / 8, 256>>>();
    // K1: bf16 MMA scores (cp.async + ldmatrix) -> gmem + blockmax
    score_mma<<<dim3(NTOK / 128, VOCP / 128), 256>>>(zih, zch, scores, bmax);
    // K2: block-select + prune + exact top-4 + histogram
    select_k<<<NTOK / 4, 128>>>(bmax, scores, zi, zc);
    // fused tail: quantize + STE out + mse1 + mse2
    tail_k<<<NTOK / 8, 256>>>(x, cb, out, zc, zcn, zi_pre);
    ent_k<<<64, 256>>>();
    fin_k<<<1, 1>>>(out + (size_t)NTOK * DDIM);
}

// round 16
// speedup vs baseline: 1.4216x; 1.0077x over previous
#include <cuda_runtime.h>
#include <cuda_bf16.h>
#include <math.h>
#include <float.h>
#include <limits.h>
#include <stdint.h>

// Problem constants
#define NTOK 4096      // B*S
#define DDIM 768
#define LDIM 256
#define VOC  50265
#define VOCP 50304     // 393 tiles of 128
#define NBLK 786       // 64-code blocks (VOCP/64)
#define BMAXP 788      // padded row
#define KSEL 4
#define NCAND 24
#define ZC_BLKS 393    // ceil(VOC/128)
#define ZI_BLKS 32     // NTOK/128

// ---------------- scratch (device globals; no allocations) ----------------
__device__ float  g_zi_pre[NTOK * LDIM];      // x@W_in+b (kept for mse2 ref)
__device__ float  g_zi[NTOK * LDIM];          // normalized
__device__ float  g_zc[VOC * LDIM];           // normalized latent codebook
__device__ float  g_zcn[VOC];                 // reciprocal norm: zc_pre = zc * g_zcn
__device__ __nv_bfloat16 g_zih[NTOK * LDIM];
__device__ __nv_bfloat16 g_zch[VOC * LDIM];
__device__ __nv_bfloat16 g_wth[LDIM * DDIM];  // W_code^T hi (n-major, k-contig)
__device__ __nv_bfloat16 g_wtl[LDIM * DDIM];  // W_code^T lo
__device__ __nv_bfloat16 g_wih[LDIM * DDIM];  // W_in^T hi
__device__ __nv_bfloat16 g_wil[LDIM * DDIM];  // W_in^T lo
__device__ __nv_bfloat16 g_scores[(size_t)NTOK * VOCP];   // all approx scores
__device__ __nv_bfloat16 g_bmax[(size_t)NTOK * BMAXP];    // per-64-block max
__device__ int    g_idx[NTOK * KSEL];
__device__ int    g_counts[VOC];
__device__ double g_mse1, g_mse2, g_ent;
__device__ int    g_nz;

// ---------------- helpers ----------------
__device__ __forceinline__ uint32_t smem_u32(const void* p) {
    uint32_t a;
    asm("{ .reg .u64 t; cvta.to.shared.u64 t, %1; cvt.u32.u64 %0, t; }" : "=r"(a) : "l"(p));
    return a;
}
__device__ __forceinline__ bool better(float v, int j, float v2, int j2) {
    return (v > v2) || (v == v2 && j < j2);
}
template <int K>
__device__ __forceinline__ void insK(float v, int j, float tv[K], int ti[K]) {
    if (!better(v, j, tv[K-1], ti[K-1])) return;
    tv[K-1] = v; ti[K-1] = j;
#pragma unroll
    for (int k = K-1; k > 0; k--) {
        if (better(tv[k], ti[k], tv[k-1], ti[k-1])) {
            float fv = tv[k]; tv[k] = tv[k-1]; tv[k-1] = fv;
            int   fi = ti[k]; ti[k] = ti[k-1]; ti[k-1] = fi;
        }
    }
}

// ---------------- bf16 mma + ldmatrix + cp.async helpers ----------------
__device__ __forceinline__ void mma_bf16(float d[4], const unsigned a[4], const unsigned b[2]) {
    asm("mma.sync.aligned.m16n8k16.row.col.f32.bf16.bf16.f32 "
        "{%0,%1,%2,%3},{%4,%5,%6,%7},{%8,%9},{%0,%1,%2,%3};"
        : "+f"(d[0]), "+f"(d[1]), "+f"(d[2]), "+f"(d[3])
        : "r"(a[0]), "r"(a[1]), "r"(a[2]), "r"(a[3]), "r"(b[0]), "r"(b[1]));
}
__device__ __forceinline__ void ldsm_x4(uint32_t addr, unsigned r[4]) {
    asm volatile("ldmatrix.sync.aligned.m8n8.x4.shared.b16 {%0,%1,%2,%3}, [%4];"
        : "=r"(r[0]), "=r"(r[1]), "=r"(r[2]), "=r"(r[3]) : "r"(addr));
}
__device__ __forceinline__ void cp16(uint32_t dst, const void* src, int ssz) {
    asm volatile("cp.async.cg.shared.global [%0], [%1], 16, %2;"
        :: "r"(dst), "l"(src), "r"(ssz) : "memory");
}
#define CP_COMMIT() asm volatile("cp.async.commit_group;" ::: "memory")
#define CP_WAIT0()  asm volatile("cp.async.wait_group 0;" ::: "memory")

// ---------------- fused prep kernel: W transposes + init -------------------
// blocks [0,64) Wi T-split, [64,128) Wc T-split, [128,192) init counts/scalars
__device__ __forceinline__ void split_transpose(const float* W, __nv_bfloat16* wh,
                                                __nv_bfloat16* wl, int bid, int nblk)
{
    int i = bid * blockDim.x + threadIdx.x;
    int stride = nblk * blockDim.x;
    for (; i < LDIM * DDIM; i += stride) {
        int n = i / DDIM, k = i - n * DDIM;
        float v = W[k * LDIM + n];
        __nv_bfloat16 h = __float2bfloat16(v);
        wh[i] = h;
        wl[i] = __float2bfloat16(v - __bfloat162float(h));
    }
}
__global__ void prep_k(const float* __restrict__ Wi, const float* __restrict__ Wc)
{
    int b = blockIdx.x;
    if (b < 64)
        split_transpose(Wi, g_wih, g_wil, b, 64);
    else if (b < 128)
        split_transpose(Wc, g_wth, g_wtl, b - 64, 64);
    else {
        int i = (b - 128) * blockDim.x + threadIdx.x;
        for (int v = i; v < VOC; v += 64 * blockDim.x) g_counts[v] = 0;
        if (i == 0) { g_mse1 = 0.0; g_mse2 = 0.0; g_ent = 0.0; g_nz = 0; }
    }
}

// ---------------- merged projection GEMM (zc + zi), fused A-split ----------
// blocks [0,393): zc rows (cb @ Wc + bc); [393,425): zi rows (x @ Wi + bi)
// A is fp32 in gmem; staged via cp.async, converted to bf16 hi/lo in-kernel.
// 3-product bf16-split MMA, K=768 in 24 double-buffered 32-k stages.
// smem layout: fA0 @0 (128x144), fA1 @18432, Ah @36864 (128x80), Al @47104,
//              Bh0 @57344, Bl0 @67584, Bh1 @77824, Bl1 @88064 ; total 98304.
__global__ void __launch_bounds__(256, 2)
proj_mma(const float* __restrict__ cbf, const float* __restrict__ xf,
         const float* __restrict__ bc, const float* __restrict__ bi)
{
    extern __shared__ __align__(16) char dynbuf[];
    const int tid = threadIdx.x;
    const int w = tid >> 5, lane = tid & 31;
    const int grp = lane >> 2, tig = lane & 3;
    const int wm = w >> 1, wn = w & 1;            // 4 x 2 warp grid
    const int bx = blockIdx.x;
    const float* A_g;
    const __nv_bfloat16 *bh_g, *bl_g;
    const float* bias;
    float* C;
    int Mrows, m0;
    if (bx < ZC_BLKS) {
        A_g = cbf; bh_g = g_wth; bl_g = g_wtl;
        bias = bc; C = g_zc; Mrows = VOC; m0 = bx * 128;
    } else {
        A_g = xf; bh_g = g_wih; bl_g = g_wil;
        bias = bi; C = g_zi_pre; Mrows = NTOK; m0 = (bx - ZC_BLKS) * 128;
    }
    const int n0 = blockIdx.y * 128;
    const int lrow = tid >> 1;                    // loader row 0..127
    const int half = tid & 1;

    const uint32_t sm0 = smem_u32(dynbuf);
    const uint32_t fA[2]  = {sm0,          sm0 + 18432};
    const uint32_t sAh    = sm0 + 36864;
    const uint32_t sAl    = sm0 + 47104;
    const uint32_t sBh[2] = {sm0 + 57344, sm0 + 77824};
    const uint32_t sBl[2] = {sm0 + 67584, sm0 + 88064};

    const uint32_t fdst = (uint32_t)(lrow * 144 + half * 64);   // fp32 A stage
    const uint32_t ldst = (uint32_t)(lrow * 80 + half * 32);    // bf16 buffers

    uint32_t offA[2], offB[4];
    {
        int la = lane & 15, ha = lane >> 4;
#pragma unroll
        for (int mi = 0; mi < 2; mi++)
            offA[mi] = (uint32_t)((wm * 32 + mi * 16 + la) * 80 + ha * 16);
        int rb = ((lane >> 4) & 1) * 8 + (lane & 7);
        int cbb = ((lane >> 3) & 1) * 16;
#pragma unroll
        for (int p = 0; p < 4; p++)
            offB[p] = (uint32_t)((wn * 64 + p * 16 + rb) * 80 + cbb);
    }

    float acc[2][8][4] = {};
    const int asz = (m0 + lrow < Mrows) ? 16 : 0; // zero-fill OOB rows
    const float* a_src = A_g + (size_t)(m0 + lrow) * DDIM + half * 16;
    const __nv_bfloat16* bh_src = bh_g + (size_t)(n0 + lrow) * DDIM + half * 16;
    const __nv_bfloat16* bl_src = bl_g + (size_t)(n0 + lrow) * DDIM + half * 16;

    // prologue: async stage 0 (A fp32 64B/thread + B bf16 32B/thread each)
    {
        cp16(fA[0] + fdst,      a_src,      asz);
        cp16(fA[0] + fdst + 16, a_src + 4,  asz);
        cp16(fA[0] + fdst + 32, a_src + 8,  asz);
        cp16(fA[0] + fdst + 48, a_src + 12, asz);
        cp16(sBh[0] + ldst,      bh_src,     16);
        cp16(sBh[0] + ldst + 16, bh_src + 8, 16);
        cp16(sBl[0] + ldst,      bl_src,     16);
        cp16(sBl[0] + ldst + 16, bl_src + 8, 16);
        CP_COMMIT();
    }

    for (int s = 0; s < 24; s++) {           // 24 stages of 32 k-dims
        CP_WAIT0();
        __syncthreads();                      // stage s data ready; prev ldsm done
        if (s < 23) {
            int ko = (s + 1) * 32;
            int par = (s + 1) & 1;
            cp16(fA[par] + fdst,      a_src + ko,      asz);
            cp16(fA[par] + fdst + 16, a_src + ko + 4,  asz);
            cp16(fA[par] + fdst + 32, a_src + ko + 8,  asz);
            cp16(fA[par] + fdst + 48, a_src + ko + 12, asz);
            cp16(sBh[par] + ldst,      bh_src + ko,     16);
            cp16(sBh[par] + ldst + 16, bh_src + ko + 8, 16);
            cp16(sBl[par] + ldst,      bl_src + ko,     16);
            cp16(sBl[par] + ldst + 16, bl_src + ko + 8, 16);
            CP_COMMIT();
        }
        // convert fp32 stage -> Ah/Al (16 floats per thread, identity layout)
        {
            const uint32_t src = fA[s & 1] + fdst;
            unsigned hw[8], lw[8];
#pragma unroll
            for (int q = 0; q < 4; q++) {
                float4 v;
                asm volatile("ld.shared.v4.f32 {%0,%1,%2,%3}, [%4];"
                    : "=f"(v.x), "=f"(v.y), "=f"(v.z), "=f"(v.w)
                    : "r"(src + q * 16));
                __nv_bfloat16 h0 = __float2bfloat16(v.x);
                __nv_bfloat16 h1 = __float2bfloat16(v.y);
                __nv_bfloat16 h2 = __float2bfloat16(v.z);
                __nv_bfloat16 h3 = __float2bfloat16(v.w);
                __nv_bfloat16 l0 = __float2bfloat16(v.x - __bfloat162float(h0));
                __nv_bfloat16 l1 = __float2bfloat16(v.y - __bfloat162float(h1));
                __nv_bfloat16 l2 = __float2bfloat16(v.z - __bfloat162float(h2));
                __nv_bfloat16 l3 = __float2bfloat16(v.w - __bfloat162float(h3));
                __nv_bfloat162 hp0 = {h0, h1}, hp1 = {h2, h3};
                __nv_bfloat162 lp0 = {l0, l1}, lp1 = {l2, l3};
                hw[2*q]     = *(unsigned*)&hp0;
                hw[2*q + 1] = *(unsigned*)&hp1;
                lw[2*q]     = *(unsigned*)&lp0;
                lw[2*q + 1] = *(unsigned*)&lp1;
            }
            asm volatile("st.shared.v4.b32 [%0], {%1,%2,%3,%4};"
                :: "r"(sAh + ldst), "r"(hw[0]), "r"(hw[1]), "r"(hw[2]), "r"(hw[3]));
            asm volatile("st.shared.v4.b32 [%0], {%1,%2,%3,%4};"
                :: "r"(sAh + ldst + 16), "r"(hw[4]), "r"(hw[5]), "r"(hw[6]), "r"(hw[7]));
            asm volatile("st.shared.v4.b32 [%0], {%1,%2,%3,%4};"
                :: "r"(sAl + ldst), "r"(lw[0]), "r"(lw[1]), "r"(lw[2]), "r"(lw[3]));
            asm volatile("st.shared.v4.b32 [%0], {%1,%2,%3,%4};"
                :: "r"(sAl + ldst + 16), "r"(lw[4]), "r"(lw[5]), "r"(lw[6]), "r"(lw[7]));
        }
        __syncthreads();                      // Ah/Al ready for ldmatrix
        const uint32_t bh_ = sBh[s & 1], bl_ = sBl[s & 1];
#pragma unroll
        for (int ks = 0; ks < 2; ks++) {
            unsigned ah0[4], ah1[4], al0[4], al1[4];
            ldsm_x4(sAh + offA[0] + ks * 32, ah0);
            ldsm_x4(sAh + offA[1] + ks * 32, ah1);
            ldsm_x4(sAl + offA[0] + ks * 32, al0);
            ldsm_x4(sAl + offA[1] + ks * 32, al1);
#pragma unroll
            for (int p = 0; p < 4; p++) {
                unsigned bh[4], bl[4];
                ldsm_x4(bh_ + offB[p] + ks * 32, bh);
                ldsm_x4(bl_ + offB[p] + ks * 32, bl);
                mma_bf16(acc[0][2*p],     ah0, bh);
                mma_bf16(acc[0][2*p + 1], ah0, bh + 2);
                mma_bf16(acc[1][2*p],     ah1, bh);
                mma_bf16(acc[1][2*p + 1], ah1, bh + 2);
                mma_bf16(acc[0][2*p],     ah0, bl);
                mma_bf16(acc[0][2*p + 1], ah0, bl + 2);
                mma_bf16(acc[1][2*p],     ah1, bl);
                mma_bf16(acc[1][2*p + 1], ah1, bl + 2);
                mma_bf16(acc[0][2*p],     al0, bh);
                mma_bf16(acc[0][2*p + 1], al0, bh + 2);
                mma_bf16(acc[1][2*p],     al1, bh);
                mma_bf16(acc[1][2*p + 1], al1, bh + 2);
            }
        }
    }

#pragma unroll
    for (int mi = 0; mi < 2; mi++)
#pragma unroll
    for (int h = 0; h < 2; h++) {
        int row = m0 + wm * 32 + mi * 16 + grp + h * 8;
        if (row < Mrows) {
#pragma unroll
            for (int ni = 0; ni < 8; ni++) {
                int col = n0 + wn * 64 + ni * 8 + tig * 2;
                float2 v;
                v.x = acc[mi][ni][2*h]     + bias[col];
                v.y = acc[mi][ni][2*h + 1] + bias[col + 1];
                *(float2*)&C[(size_t)row * LDIM + col] = v;
            }
        }
    }
}

// ---------------- merged row L2-normalize (zi rows then zc rows) -----------
__global__ void norm_k()
{
    int w = (blockIdx.x * blockDim.x + threadIdx.x) >> 5;
    int lane = threadIdx.x & 31;
    if (w >= NTOK + VOC) return;
    const float* in;
    float* out;
    __nv_bfloat16* oh;
    bool zc_path = (w >= NTOK);
    int row = zc_path ? (w - NTOK) : w;
    if (zc_path) { in = g_zc;     out = g_zc; oh = g_zch; }
    else         { in = g_zi_pre; out = g_zi; oh = g_zih; }
    const float* r = in + (size_t)row * LDIM;
    float vals[8];
    float s = 0.f;
#pragma unroll
    for (int i = 0; i < 8; i++) { vals[i] = r[lane + 32 * i]; s += vals[i] * vals[i]; }
#pragma unroll
    for (int off = 16; off > 0; off >>= 1)
        s += __shfl_xor_sync(0xFFFFFFFFu, s, off);
    float t = s + 1e-12f;
    float sc = rsqrtf(t);
    sc = sc * (1.5f - 0.5f * t * sc * sc);   // Newton: ~1 ulp
    float* o = out + (size_t)row * LDIM;
    __nv_bfloat16* ohp = oh + (size_t)row * LDIM;
#pragma unroll
    for (int i = 0; i < 8; i++) {
        float v = vals[i] * sc;
        o[lane + 32 * i] = v;
        ohp[lane + 32 * i] = __float2bfloat16(v);
    }
    if (zc_path && lane == 0) g_zcn[row] = 1.0f / sc;
}

// ---------------- K1: MMA scores -> bf16 store + 64-block max --------------
__global__ void __launch_bounds__(256, 2)
score_mma(const __nv_bfloat16* __restrict__ zih, const __nv_bfloat16* __restrict__ zch,
          __nv_bfloat16* __restrict__ scores, __nv_bfloat16* __restrict__ bmax)
{
    __shared__ __align__(16) char smembuf[40960];
    const int tid = threadIdx.x;
    const int w = tid >> 5, lane = tid & 31;
    const int grp = lane >> 2, tig = lane & 3;
    const int wm = w >> 1, wn = w & 1;            // 4 x 2 warp grid
    const int t0 = blockIdx.x * 128;
    const int jc = blockIdx.y * 128;

    const int lrow = tid >> 1;                    // loader row 0..127
    const int eo   = (tid & 1) * 16;

    const uint32_t sm0 = smem_u32(smembuf);
    const uint32_t stA[2] = {sm0,         sm0 + 10240};
    const uint32_t stB[2] = {sm0 + 20480, sm0 + 30720};

    uint32_t offA[2], offB[4];
    {
        int la = lane & 15, ha = lane >> 4;       // A: row sel, k half
#pragma unroll
        for (int mi = 0; mi < 2; mi++)
            offA[mi] = (uint32_t)((wm * 32 + mi * 16 + la) * 80 + ha * 16);
        int rb = ((lane >> 4) & 1) * 8 + (lane & 7);
        int cbb = ((lane >> 3) & 1) * 16;
#pragma unroll
        for (int p = 0; p < 4; p++)
            offB[p] = (uint32_t)((wn * 64 + p * 16 + rb) * 80 + cbb);
    }

    float acc[2][8][4] = {};
    int jrow = jc + lrow;
    const int bsz = (jrow < VOC) ? 16 : 0;        // cp.async zero-fill OOB rows
    const __nv_bfloat16* arow = zih + (size_t)(t0 + lrow) * LDIM + eo;
    const __nv_bfloat16* brow = zch + (size_t)jrow * LDIM + eo;
    const uint32_t ldst = (uint32_t)(lrow * 80 + eo * 2);

    // prologue: async stage 0
    cp16(stA[0] + ldst,      arow,     16);
    cp16(stA[0] + ldst + 16, arow + 8, 16);
    cp16(stB[0] + ldst,      brow,     bsz);
    cp16(stB[0] + ldst + 16, brow + 8, bsz);
    CP_COMMIT();

#pragma unroll
    for (int s = 0; s < 8; s++) {            // 8 stages of 32 k-dims
        CP_WAIT0();
        __syncthreads();
        if (s < 7) {                         // async prefetch next stage
            int ko = (s + 1) * 32;
            uint32_t dA = stA[(s + 1) & 1] + ldst;
            uint32_t dB = stB[(s + 1) & 1] + ldst;
            cp16(dA,      arow + ko,     16);
            cp16(dA + 16, arow + ko + 8, 16);
            cp16(dB,      brow + ko,     bsz);
            cp16(dB + 16, brow + ko + 8, bsz);
            CP_COMMIT();
        }
        const uint32_t sA = stA[s & 1], sB = stB[s & 1];
#pragma unroll
        for (int ks = 0; ks < 2; ks++) {
            unsigned a0[4], a1[4];
            ldsm_x4(sA + offA[0] + ks * 32, a0);
            ldsm_x4(sA + offA[1] + ks * 32, a1);
#pragma unroll
            for (int p = 0; p < 4; p++) {
                unsigned bb[4];
                ldsm_x4(sB + offB[p] + ks * 32, bb);
                mma_bf16(acc[0][2*p],     a0, bb);
                mma_bf16(acc[0][2*p + 1], a0, bb + 2);
                mma_bf16(acc[1][2*p],     a1, bb);
                mma_bf16(acc[1][2*p + 1], a1, bb + 2);
            }
        }
    }

    // ---- epilogue: cvt bf16, store, packed block-max (no syncs needed) ----
    const int colbase = wn * 64 + tig * 2;
#pragma unroll
    for (int mi = 0; mi < 2; mi++)
#pragma unroll
    for (int h = 0; h < 2; h++) {
        int row_l = wm * 32 + mi * 16 + grp + h * 8;
        size_t rowoff = (size_t)(t0 + row_l) * VOCP;
        unsigned p[8];
#pragma unroll
        for (int ni = 0; ni < 8; ni++) {
            float2 f2 = make_float2(acc[mi][ni][2*h], acc[mi][ni][2*h + 1]);
            __nv_bfloat162 bb = __float22bfloat162_rn(f2);   // .x -> low half
            p[ni] = *(unsigned*)&bb;
        }
        if (jc + 128 > VOC) {        // mask tail columns with bf16 -inf
#pragma unroll
            for (int ni = 0; ni < 8; ni++) {
                int j = jc + colbase + ni * 8;
                if (j >= VOC)     p[ni] = (p[ni] & 0xFFFF0000u) | 0x0000FF80u;
                if (j + 1 >= VOC) p[ni] = (p[ni] & 0x0000FFFFu) | 0xFF800000u;
            }
        }
#pragma unroll
        for (int ni = 0; ni < 8; ni++)
            *(unsigned*)(scores + rowoff + jc + colbase + ni * 8) = p[ni];
        __nv_bfloat162 m = *(__nv_bfloat162*)&p[0];
#pragma unroll
        for (int ni = 1; ni < 8; ni++) m = __hmax2(m, *(__nv_bfloat162*)&p[ni]);
        unsigned mu = *(unsigned*)&m;
        unsigned o1 = __shfl_xor_sync(0xFFFFFFFFu, mu, 1);
        m = __hmax2(m, *(__nv_bfloat162*)&o1);
        mu = *(unsigned*)&m;
        unsigned o2 = __shfl_xor_sync(0xFFFFFFFFu, mu, 2);
        m = __hmax2(m, *(__nv_bfloat162*)&o2);
        if (tig == 0) {
            __nv_bfloat16 ms = __hmax(m.x, m.y);
            bmax[(size_t)(t0 + row_l) * BMAXP + (jc >> 6) + wn] = ms;
        }
    }
}

// ---------------- K2: block select + candidate prune + exact top-4 --------
__global__ void __launch_bounds__(128)
select_k(const __nv_bfloat16* __restrict__ bmax, const __nv_bfloat16* __restrict__ scores,
         const float* __restrict__ zi, const float* __restrict__ zc)
{
    __shared__ int scand[4][NCAND];
    const int wl = threadIdx.x >> 5;
    const int t = (blockIdx.x * blockDim.x + threadIdx.x) >> 5;
    const int lane = threadIdx.x & 31;
    if (t >= NTOK) return;

    // Phase A: lane-local top-8 of 786 blockmaxes
    float lv[8]; int lb[8];
#pragma unroll
    for (int k = 0; k < 8; k++) { lv[k] = -FLT_MAX; lb[k] = INT_MAX; }
    const __nv_bfloat16* bm = bmax + (size_t)t * BMAXP;
#pragma unroll
    for (int k = 0; k < 25; k++) {
        int b = lane + 32 * k;
        if (b < NBLK) {
            float v = __bfloat162float(bm[b]);
            if (v >= lv[7]) insK<8>(v, b, lv, lb);
        }
    }
    // extract top-16 blocks (warp-wide argmax, owner pops)
    int blk[16];
#pragma unroll
    for (int r = 0; r < 16; r++) {
        float cv = lv[0]; int cb = lb[0];
#pragma unroll
        for (int off = 16; off > 0; off >>= 1) {
            float ov = __shfl_xor_sync(0xFFFFFFFFu, cv, off);
            int   ob = __shfl_xor_sync(0xFFFFFFFFu, cb, off);
            if (better(ov, ob, cv, cb)) { cv = ov; cb = ob; }
        }
        blk[r] = cb;
        if (lb[0] == cb) {
#pragma unroll
            for (int k = 0; k < 7; k++) { lv[k] = lv[k+1]; lb[k] = lb[k+1]; }
            lv[7] = -FLT_MAX; lb[7] = INT_MAX;
        }
    }

    // Phase B: lane-local top-12 over the 16 blocks' 1024 bf16 scores
    float cv12[12]; int ci12[12];
#pragma unroll
    for (int k = 0; k < 12; k++) { cv12[k] = -FLT_MAX; ci12[k] = INT_MAX; }
    const __nv_bfloat16* srow = scores + (size_t)t * VOCP;
#pragma unroll
    for (int r = 0; r < 16; r++) {
        int j0 = blk[r] * 64 + lane * 2;
        unsigned u = *(const unsigned*)(srow + j0);
        __nv_bfloat162 b2 = *(__nv_bfloat162*)&u;
        float f0 = __bfloat162float(b2.x);
        float f1 = __bfloat162float(b2.y);
        if (f0 >= cv12[11]) insK<12>(f0, j0,     cv12, ci12);
        if (f1 >= cv12[11]) insK<12>(f1, j0 + 1, cv12, ci12);
    }
    // Phase C: extract top-24 candidates into smem
#pragma unroll
    for (int r = 0; r < NCAND; r++) {
        float cv = cv12[0]; int cb = ci12[0];
#pragma unroll
        for (int off = 16; off > 0; off >>= 1) {
            float ov = __shfl_xor_sync(0xFFFFFFFFu, cv, off);
            int   ob = __shfl_xor_sync(0xFFFFFFFFu, cb, off);
            if (better(ov, ob, cv, cb)) { cv = ov; cb = ob; }
        }
        if (lane == 0) scand[wl][r] = cb;
        if (ci12[0] == cb) {
#pragma unroll
            for (int k = 0; k < 11; k++) { cv12[k] = cv12[k+1]; ci12[k] = ci12[k+1]; }
            cv12[11] = -FLT_MAX; ci12[11] = INT_MAX;
        }
    }
    __syncwarp();

    // Phase D: exact fp32 rescore of 24 candidates -> top-4 + histogram
    const float* zr = zi + (size_t)t * LDIM;
    float a[8];
#pragma unroll
    for (int i = 0; i < 8; i++) a[i] = zr[lane + 32 * i];
    float tv[4] = {-FLT_MAX, -FLT_MAX, -FLT_MAX, -FLT_MAX};
    int   ti[4] = {INT_MAX, INT_MAX, INT_MAX, INT_MAX};
    for (int c = 0; c < NCAND; c += 2) {
        int j0c = scand[wl][c], j1c = scand[wl][c + 1];
        const float* b0 = zc + (size_t)j0c * LDIM;
        const float* b1 = zc + (size_t)j1c * LDIM;
        float s0 = 0.f, s1 = 0.f;
#pragma unroll
        for (int i = 0; i < 8; i++) {
            s0 += a[i] * b0[lane + 32 * i];
            s1 += a[i] * b1[lane + 32 * i];
        }
#pragma unroll
        for (int off = 16; off > 0; off >>= 1) {
            s0 += __shfl_xor_sync(0xFFFFFFFFu, s0, off);
            s1 += __shfl_xor_sync(0xFFFFFFFFu, s1, off);
        }
        insK<4>(s0, j0c, tv, ti);
        insK<4>(s1, j1c, tv, ti);
    }
    if (lane == 0) {
#pragma unroll
        for (int k = 0; k < 4; k++) {
            g_idx[t * 4 + k] = ti[k];
            atomicAdd(&g_counts[ti[k]], 1);
        }
    }
}

// ---------------- fused tail: quantize + STE out + mse1 + mse2 -------------
__global__ void tail_k(const float* __restrict__ x, const float* __restrict__ cb,
                       float* __restrict__ out, const float* __restrict__ zc,
                       const float* __restrict__ rn, const float* __restrict__ zi_pre)
{
    int w = (blockIdx.x * blockDim.x + threadIdx.x) >> 5;   // token
    int lane = threadIdx.x & 31;
    if (w >= NTOK) return;
    int j0 = g_idx[w * 4 + 0], j1 = g_idx[w * 4 + 1];
    int j2 = g_idx[w * 4 + 2], j3 = g_idx[w * 4 + 3];
    const float* c0 = cb + (size_t)j0 * DDIM;
    const float* c1 = cb + (size_t)j1 * DDIM;
    const float* c2 = cb + (size_t)j2 * DDIM;
    const float* c3 = cb + (size_t)j3 * DDIM;
    double s = 0.0;
    for (int c = lane; c < DDIM; c += 32) {
        float qv = (((c0[c] + c1[c]) + c2[c]) + c3[c]) * 0.25f;
        float xv = x[(size_t)w * DDIM + c];
        float d = qv - xv;
        out[(size_t)w * DDIM + c] = xv + d;     // x + (q - x), matches STE
        s += (double)d * (double)d;
    }
    float w0 = 0.25f * rn[j0], w1 = 0.25f * rn[j1];
    float w2 = 0.25f * rn[j2], w3 = 0.25f * rn[j3];
    const float* z0 = zc + (size_t)j0 * LDIM;
    const float* z1 = zc + (size_t)j1 * LDIM;
    const float* z2 = zc + (size_t)j2 * LDIM;
    const float* z3 = zc + (size_t)j3 * LDIM;
    const float* rp = zi_pre + (size_t)w * LDIM;
    double s2 = 0.0;
#pragma unroll
    for (int i = 0; i < 8; i++) {
        int c = lane + 32 * i;
        float v = z0[c] * w0 + z1[c] * w1 + z2[c] * w2 + z3[c] * w3 - rp[c];
        s2 += (double)v * (double)v;
    }
#pragma unroll
    for (int off = 16; off > 0; off >>= 1) {
        s  += __shfl_down_sync(0xFFFFFFFFu, s, off);
        s2 += __shfl_down_sync(0xFFFFFFFFu, s2, off);
    }
    if (lane == 0) { atomicAdd(&g_mse1, s); atomicAdd(&g_mse2, s2); }
}

// ---------------- entropy / usage ------------------------------------------
__global__ void ent_k()
{
    int i0 = blockIdx.x * blockDim.x + threadIdx.x;
    double e = 0.0; int nz = 0;
    for (int i = i0; i < VOC; i += gridDim.x * blockDim.x) {
        int c = g_counts[i];
        if (c > 0) {
            float p = (float)c * (1.0f / (NTOK * KSEL));
            e += (double)(p * logf(p + 1e-10f));
            nz++;
        }
    }
#pragma unroll
    for (int off = 16; off > 0; off >>= 1) {
        e  += __shfl_down_sync(0xFFFFFFFFu, e, off);
        nz += __shfl_down_sync(0xFFFFFFFFu, nz, off);
    }
    if ((threadIdx.x & 31) == 0) { atomicAdd(&g_ent, e); atomicAdd(&g_nz, nz); }
}

// ---------------- finalize scalars -----------------------------------------
__global__ void fin_k(float* __restrict__ out3)
{
    float lp = (float)(-g_ent);
    float mse1 = (float)(g_mse1 / ((double)NTOK * DDIM));
    float mse2 = (float)(g_mse2 / ((double)NTOK * LDIM));
    float loss = 1.25f * mse1 + 1.25f * mse2 + 0.1f * lp;
    out3[0] = loss;
    out3[1] = expf(lp);
    out3[2] = (float)g_nz / (float)VOC / (float)KSEL;
}

// ---------------- launch ----------------------------------------------------
static float* sym_f(const void* s) { void* p = nullptr; cudaGetSymbolAddress(&p, s); return (float*)p; }
static __nv_bfloat16* sym_b(const void* s) { void* p = nullptr; cudaGetSymbolAddress(&p, s); return (__nv_bfloat16*)p; }

#define PROJ_SMEM 98304

extern "C" void kernel_launch(void* const* d_in, const int* in_sizes, int n_in,
                              void* d_out, int out_size)
{
    const float* x  = (const float*)d_in[0];
    const float* cb = (const float*)d_in[1];
    const float* Wi = (const float*)d_in[2];
    const float* bi = (const float*)d_in[3];
    const float* Wc = (const float*)d_in[4];
    const float* bc = (const float*)d_in[5];
    float* out = (float*)d_out;

    float* zi_pre = sym_f(g_zi_pre);
    float* zi     = sym_f(g_zi);
    float* zc     = sym_f(g_zc);
    float* zcn    = sym_f(g_zcn);
    __nv_bfloat16* zih = sym_b(g_zih);
    __nv_bfloat16* zch = sym_b(g_zch);
    __nv_bfloat16* scores = sym_b(g_scores);
    __nv_bfloat16* bmax   = sym_b(g_bmax);

    cudaFuncSetAttribute(proj_mma, cudaFuncAttributeMaxDynamicSharedMemorySize, PROJ_SMEM);

    // prep: W transposes + histogram/scalar init
    prep_k<<<192, 256>>>(Wi, Wc);
    // merged projections with fused fp32->bf16hi/lo A conversion
    proj_mma<<<dim3(ZC_BLKS + ZI_BLKS, LDIM / 128), 256, PROJ_SMEM>>>(cb, x, bc, bi);
    // merged normalize: zi rows then zc rows (+ bf16 copies, zc recip norms)
    norm_k<<<(NTOK + VOC + 7) / 8, 256>>>();
    // K1: bf16 MMA scores (cp.async + ldmatrix) -> gmem + blockmax
    score_mma<<<dim3(NTOK / 128, VOCP / 128), 256>>>(zih, zch, scores, bmax);
    // K2: block-select + prune + exact top-4 + histogram
    select_k<<<NTOK / 4, 128>>>(bmax, scores, zi, zc);
    // fused tail: quantize + STE out + mse1 + mse2
    tail_k<<<NTOK / 8, 256>>>(x, cb, out, zc, zcn, zi_pre);
    ent_k<<<64, 256>>>();
    fin_k<<<1, 1>>>(out + (size_t)NTOK * DDIM);
}